// round 10
// baseline (speedup 1.0000x reference)
#include <cuda_runtime.h>
#include <cstdint>

// ---------------------------------------------------------------------------
// GCN decoder: 4 x (GCNConv [+ReLU] [+upsample x2 folded into indexing])
// Phase 0 (once): memset(cnt) -> fused build (all 4 edge lists) -> fused rsqrt
// Per layer:      GEMM(f32x2) -> warp-per-dst gather agg (fused finalize)
// No float atomics anywhere; gathers are the only irregular traffic.
// ---------------------------------------------------------------------------

#define MAXF 6400000
#define CAP  64
// per-layer node-space offsets into cnt/dinv/adj
#define NTOT 375000        // 25000 + 50000 + 100000 + 200000

__device__ __align__(256) int   g_cnt [NTOT];
__device__ __align__(256) float g_dinv[NTOT];
__device__ __align__(256) int   g_adj [(size_t)NTOT * CAP];
__device__ __align__(256) float g_hraw[MAXF];
__device__ __align__(256) float g_p1  [MAXF];
__device__ __align__(256) float g_p2  [MAXF];

// ---------------- fused adjacency build (all 4 layers) ----------------

__global__ void k_build_all(const int* __restrict__ e1,
                            const int* __restrict__ e2,
                            const int* __restrict__ e3,
                            const int* __restrict__ e4,
                            int E1, int E2, int E3, int E4,
                            int* __restrict__ cnt,
                            int* __restrict__ adj) {
    int i = blockIdx.x * blockDim.x + threadIdx.x;
    const int* src; const int* dst; int base; int e;
    if (i < E1)                     { src = e1; dst = e1 + E1; base = 0;      e = i; }
    else if ((i -= E1) < E2)        { src = e2; dst = e2 + E2; base = 25000;  e = i; }
    else if ((i -= E2) < E3)        { src = e3; dst = e3 + E3; base = 75000;  e = i; }
    else if ((i -= E3) < E4)        { src = e4; dst = e4 + E4; base = 175000; e = i; }
    else return;
    int d = base + dst[e];
    int p = atomicAdd(&cnt[d], 1);
    if (p < CAP) adj[(size_t)d * CAP + p] = src[e];
}

__global__ void k_rsqrt_all(const int* __restrict__ cnt,
                            float* __restrict__ dinv, int M) {
    int i = blockIdx.x * blockDim.x + threadIdx.x;
    if (i < M) dinv[i] = rsqrtf((float)cnt[i] + 1.0f);
}

// ---------------- f32x2 helpers ----------------

__device__ __forceinline__ uint64_t bcast_f32x2(float x) {
    uint64_t r;
    uint32_t b = __float_as_uint(x);
    asm("mov.b64 %0, {%1, %1};" : "=l"(r) : "r"(b));
    return r;
}

__device__ __forceinline__ void fma_f32x2(uint64_t& c, uint64_t a, uint64_t b) {
    asm("fma.rn.f32x2 %0, %1, %2, %0;" : "+l"(c) : "l"(a), "l"(b));
}

__device__ __forceinline__ float2 unpack_f32x2(uint64_t p) {
    uint32_t lo, hi;
    asm("mov.b64 {%0, %1}, %2;" : "=r"(lo), "=r"(hi) : "l"(p));
    return make_float2(__uint_as_float(lo), __uint_as_float(hi));
}

// ---------------- tiled GEMM: hraw = X @ W (f32x2, 8x4 microtile) -----------

__global__ __launch_bounds__(256) void k_gemm_tiled(
        const float* __restrict__ X,
        const float* __restrict__ W,
        float* __restrict__ hraw,
        int Mr, int K, int F) {
    __shared__ float As[16][128];
    __shared__ float Bs[16][64];

    const int tid = threadIdx.x;
    const int tx  = tid & 15;
    const int ty  = tid >> 4;
    const int row0 = blockIdx.y * 128;
    const int col0 = blockIdx.x * 64;

    const int brow = tid >> 4;
    const int bc   = (tid & 15) * 4;

    uint64_t cc[4][4] = {};

    for (int k0 = 0; k0 < K; k0 += 16) {
        #pragma unroll
        for (int li = 0; li < 2; li++) {
            int i = tid + li * 256;
            int r  = i >> 2;
            int kc = (i & 3) * 4;
            int grow = row0 + r;
            float4 v = make_float4(0.f, 0.f, 0.f, 0.f);
            if (grow < Mr)
                v = *reinterpret_cast<const float4*>(
                    X + (size_t)grow * K + k0 + kc);
            As[kc + 0][r] = v.x;
            As[kc + 1][r] = v.y;
            As[kc + 2][r] = v.z;
            As[kc + 3][r] = v.w;
        }
        *reinterpret_cast<float4*>(&Bs[brow][bc]) =
            *reinterpret_cast<const float4*>(W + (size_t)(k0 + brow) * F + col0 + bc);

        __syncthreads();

        #pragma unroll
        for (int kk = 0; kk < 16; kk++) {
            const uint64_t* ap = reinterpret_cast<const uint64_t*>(&As[kk][ty * 8]);
            uint64_t a0 = ap[0], a1 = ap[1], a2 = ap[2], a3 = ap[3];
            float4 b = *reinterpret_cast<const float4*>(&Bs[kk][tx * 4]);
            uint64_t b0 = bcast_f32x2(b.x);
            uint64_t b1 = bcast_f32x2(b.y);
            uint64_t b2 = bcast_f32x2(b.z);
            uint64_t b3 = bcast_f32x2(b.w);
            fma_f32x2(cc[0][0], a0, b0); fma_f32x2(cc[0][1], a0, b1);
            fma_f32x2(cc[0][2], a0, b2); fma_f32x2(cc[0][3], a0, b3);
            fma_f32x2(cc[1][0], a1, b0); fma_f32x2(cc[1][1], a1, b1);
            fma_f32x2(cc[1][2], a1, b2); fma_f32x2(cc[1][3], a1, b3);
            fma_f32x2(cc[2][0], a2, b0); fma_f32x2(cc[2][1], a2, b1);
            fma_f32x2(cc[2][2], a2, b2); fma_f32x2(cc[2][3], a2, b3);
            fma_f32x2(cc[3][0], a3, b0); fma_f32x2(cc[3][1], a3, b1);
            fma_f32x2(cc[3][2], a3, b2); fma_f32x2(cc[3][3], a3, b3);
        }
        __syncthreads();
    }

    #pragma unroll
    for (int p = 0; p < 4; p++) {
        float2 v0 = unpack_f32x2(cc[p][0]);
        float2 v1 = unpack_f32x2(cc[p][1]);
        float2 v2 = unpack_f32x2(cc[p][2]);
        float2 v3 = unpack_f32x2(cc[p][3]);
        int rowA = row0 + ty * 8 + 2 * p;
        int rowB = rowA + 1;
        if (rowA < Mr) {
            float4 o = make_float4(v0.x, v1.x, v2.x, v3.x);
            *reinterpret_cast<float4*>(hraw + (size_t)rowA * F + col0 + tx * 4) = o;
        }
        if (rowB < Mr) {
            float4 o = make_float4(v0.y, v1.y, v2.y, v3.y);
            *reinterpret_cast<float4*>(hraw + (size_t)rowB * F + col0 + tx * 4) = o;
        }
    }
}

// ---------------- small-F GEMM (layer 4: K=64, F=8) -------------------------

__global__ void k_gemm_small(const float* __restrict__ X,
                             const float* __restrict__ W,
                             float* __restrict__ hraw,
                             int Mr, int K, int F) {
    __shared__ float Ws[512];
    for (int i = threadIdx.x; i < K * F; i += blockDim.x) Ws[i] = W[i];
    __syncthreads();

    int npb = blockDim.x / F;
    int n = blockIdx.x * npb + threadIdx.x / F;
    int f = threadIdx.x % F;
    if (n >= Mr) return;

    const float* xr = X + (size_t)n * K;
    float s = 0.f;
    #pragma unroll 8
    for (int k = 0; k < K; k++) s += xr[k] * Ws[k * F + f];

    hraw[(size_t)n * F + f] = s;
}

// ---------------- aggregation: warp per dst, MLP-unrolled edge loop ---------

template<int F>
__global__ __launch_bounds__(256) void k_agg(
        const int*   __restrict__ adj,
        const int*   __restrict__ cnt,
        const float* __restrict__ hraw,
        const float* __restrict__ dinv,
        const float* __restrict__ bias,
        float*       __restrict__ out,
        int M, int shift, int relu) {
    int w    = (blockIdx.x * blockDim.x + threadIdx.x) >> 5;
    int lane = threadIdx.x & 31;
    if (w >= M) return;
    const int d = w;
    int n = cnt[d]; if (n > CAP) n = CAP;

    constexpr int VPT = F / 32;         // 8 / 4 / 2
    float acc[VPT];
    #pragma unroll
    for (int v = 0; v < VPT; v++) acc[v] = 0.f;

    const int* ap = adj + (size_t)d * CAP;

    for (int i0 = 0; i0 < n; i0 += 32) {
        int m = n - i0; if (m > 32) m = 32;
        int e = 0; float scl = 0.f;
        if (lane < m) { e = ap[i0 + lane]; scl = dinv[e]; }

        int j = 0;
        if (F == 256) {
            for (; j + 2 <= m; j += 2) {
                int   s0 = __shfl_sync(0xffffffffu, e,   j);
                float c0 = __shfl_sync(0xffffffffu, scl, j);
                int   s1 = __shfl_sync(0xffffffffu, e,   j + 1);
                float c1 = __shfl_sync(0xffffffffu, scl, j + 1);
                const float* r0 = hraw + (size_t)(s0 >> shift) * 256;
                const float* r1 = hraw + (size_t)(s1 >> shift) * 256;
                float4 a0 = *reinterpret_cast<const float4*>(r0 + lane * 4);
                float4 b0 = *reinterpret_cast<const float4*>(r0 + 128 + lane * 4);
                float4 a1 = *reinterpret_cast<const float4*>(r1 + lane * 4);
                float4 b1 = *reinterpret_cast<const float4*>(r1 + 128 + lane * 4);
                acc[0] += c0 * a0.x; acc[1] += c0 * a0.y;
                acc[2] += c0 * a0.z; acc[3] += c0 * a0.w;
                acc[4] += c0 * b0.x; acc[5] += c0 * b0.y;
                acc[6] += c0 * b0.z; acc[7] += c0 * b0.w;
                acc[0] += c1 * a1.x; acc[1] += c1 * a1.y;
                acc[2] += c1 * a1.z; acc[3] += c1 * a1.w;
                acc[4] += c1 * b1.x; acc[5] += c1 * b1.y;
                acc[6] += c1 * b1.z; acc[7] += c1 * b1.w;
            }
        } else if (F == 128) {
            for (; j + 4 <= m; j += 4) {
                int   s0 = __shfl_sync(0xffffffffu, e,   j);
                float c0 = __shfl_sync(0xffffffffu, scl, j);
                int   s1 = __shfl_sync(0xffffffffu, e,   j + 1);
                float c1 = __shfl_sync(0xffffffffu, scl, j + 1);
                int   s2 = __shfl_sync(0xffffffffu, e,   j + 2);
                float c2 = __shfl_sync(0xffffffffu, scl, j + 2);
                int   s3 = __shfl_sync(0xffffffffu, e,   j + 3);
                float c3 = __shfl_sync(0xffffffffu, scl, j + 3);
                float4 a0 = *reinterpret_cast<const float4*>(hraw + (size_t)(s0 >> shift) * 128 + lane * 4);
                float4 a1 = *reinterpret_cast<const float4*>(hraw + (size_t)(s1 >> shift) * 128 + lane * 4);
                float4 a2 = *reinterpret_cast<const float4*>(hraw + (size_t)(s2 >> shift) * 128 + lane * 4);
                float4 a3 = *reinterpret_cast<const float4*>(hraw + (size_t)(s3 >> shift) * 128 + lane * 4);
                acc[0] += c0 * a0.x; acc[1] += c0 * a0.y; acc[2] += c0 * a0.z; acc[3] += c0 * a0.w;
                acc[0] += c1 * a1.x; acc[1] += c1 * a1.y; acc[2] += c1 * a1.z; acc[3] += c1 * a1.w;
                acc[0] += c2 * a2.x; acc[1] += c2 * a2.y; acc[2] += c2 * a2.z; acc[3] += c2 * a2.w;
                acc[0] += c3 * a3.x; acc[1] += c3 * a3.y; acc[2] += c3 * a3.z; acc[3] += c3 * a3.w;
            }
        } else {  // F == 64
            for (; j + 4 <= m; j += 4) {
                int   s0 = __shfl_sync(0xffffffffu, e,   j);
                float c0 = __shfl_sync(0xffffffffu, scl, j);
                int   s1 = __shfl_sync(0xffffffffu, e,   j + 1);
                float c1 = __shfl_sync(0xffffffffu, scl, j + 1);
                int   s2 = __shfl_sync(0xffffffffu, e,   j + 2);
                float c2 = __shfl_sync(0xffffffffu, scl, j + 2);
                int   s3 = __shfl_sync(0xffffffffu, e,   j + 3);
                float c3 = __shfl_sync(0xffffffffu, scl, j + 3);
                float2 a0 = *reinterpret_cast<const float2*>(hraw + (size_t)(s0 >> shift) * 64 + lane * 2);
                float2 a1 = *reinterpret_cast<const float2*>(hraw + (size_t)(s1 >> shift) * 64 + lane * 2);
                float2 a2 = *reinterpret_cast<const float2*>(hraw + (size_t)(s2 >> shift) * 64 + lane * 2);
                float2 a3 = *reinterpret_cast<const float2*>(hraw + (size_t)(s3 >> shift) * 64 + lane * 2);
                acc[0] += c0 * a0.x; acc[1] += c0 * a0.y;
                acc[0] += c1 * a1.x; acc[1] += c1 * a1.y;
                acc[0] += c2 * a2.x; acc[1] += c2 * a2.y;
                acc[0] += c3 * a3.x; acc[1] += c3 * a3.y;
            }
        }
        // tail
        for (; j < m; j++) {
            int   s  = __shfl_sync(0xffffffffu, e,   j);
            float sc = __shfl_sync(0xffffffffu, scl, j);
            const float* hr = hraw + (size_t)(s >> shift) * F;
            if (F == 256) {
                float4 a0 = *reinterpret_cast<const float4*>(hr + lane * 4);
                float4 b0 = *reinterpret_cast<const float4*>(hr + 128 + lane * 4);
                acc[0] += sc * a0.x; acc[1] += sc * a0.y;
                acc[2] += sc * a0.z; acc[3] += sc * a0.w;
                acc[VPT > 4 ? 4 : 0] += sc * b0.x;
                acc[VPT > 5 ? 5 : 0] += sc * b0.y;
                acc[VPT > 6 ? 6 : 0] += sc * b0.z;
                acc[VPT > 7 ? 7 : 0] += sc * b0.w;
            } else if (F == 128) {
                float4 a0 = *reinterpret_cast<const float4*>(hr + lane * 4);
                acc[0] += sc * a0.x; acc[1] += sc * a0.y;
                acc[VPT > 2 ? 2 : 0] += sc * a0.z;
                acc[VPT > 3 ? 3 : 0] += sc * a0.w;
            } else {
                float2 a0 = *reinterpret_cast<const float2*>(hr + lane * 2);
                acc[0] += sc * a0.x;
                acc[VPT > 1 ? 1 : 0] += sc * a0.y;
            }
        }
    }

    // self loop + finalize
    float dv = dinv[d];
    const float* hr = hraw + (size_t)(d >> shift) * F;
    float* op = out + (size_t)d * F;

    if (F == 256) {
        float4 h0 = *reinterpret_cast<const float4*>(hr + lane * 4);
        float4 h1 = *reinterpret_cast<const float4*>(hr + 128 + lane * 4);
        float4 b0 = *reinterpret_cast<const float4*>(bias + lane * 4);
        float4 b1 = *reinterpret_cast<const float4*>(bias + 128 + lane * 4);
        float4 o0, o1;
        o0.x = (acc[0] + dv * h0.x) * dv + b0.x;
        o0.y = (acc[1] + dv * h0.y) * dv + b0.y;
        o0.z = (acc[2] + dv * h0.z) * dv + b0.z;
        o0.w = (acc[3] + dv * h0.w) * dv + b0.w;
        o1.x = (acc[VPT > 4 ? 4 : 0] + dv * h1.x) * dv + b1.x;
        o1.y = (acc[VPT > 5 ? 5 : 0] + dv * h1.y) * dv + b1.y;
        o1.z = (acc[VPT > 6 ? 6 : 0] + dv * h1.z) * dv + b1.z;
        o1.w = (acc[VPT > 7 ? 7 : 0] + dv * h1.w) * dv + b1.w;
        if (relu) {
            o0.x = fmaxf(o0.x, 0.f); o0.y = fmaxf(o0.y, 0.f);
            o0.z = fmaxf(o0.z, 0.f); o0.w = fmaxf(o0.w, 0.f);
            o1.x = fmaxf(o1.x, 0.f); o1.y = fmaxf(o1.y, 0.f);
            o1.z = fmaxf(o1.z, 0.f); o1.w = fmaxf(o1.w, 0.f);
        }
        *reinterpret_cast<float4*>(op + lane * 4) = o0;
        *reinterpret_cast<float4*>(op + 128 + lane * 4) = o1;
    } else if (F == 128) {
        float4 h0 = *reinterpret_cast<const float4*>(hr + lane * 4);
        float4 b0 = *reinterpret_cast<const float4*>(bias + lane * 4);
        float4 o0;
        o0.x = (acc[0] + dv * h0.x) * dv + b0.x;
        o0.y = (acc[1] + dv * h0.y) * dv + b0.y;
        o0.z = (acc[VPT > 2 ? 2 : 0] + dv * h0.z) * dv + b0.z;
        o0.w = (acc[VPT > 3 ? 3 : 0] + dv * h0.w) * dv + b0.w;
        if (relu) {
            o0.x = fmaxf(o0.x, 0.f); o0.y = fmaxf(o0.y, 0.f);
            o0.z = fmaxf(o0.z, 0.f); o0.w = fmaxf(o0.w, 0.f);
        }
        *reinterpret_cast<float4*>(op + lane * 4) = o0;
    } else {  // F == 64
        float2 h0 = *reinterpret_cast<const float2*>(hr + lane * 2);
        float2 b0 = *reinterpret_cast<const float2*>(bias + lane * 2);
        float2 o0;
        o0.x = (acc[0] + dv * h0.x) * dv + b0.x;
        o0.y = (acc[VPT > 1 ? 1 : 0] + dv * h0.y) * dv + b0.y;
        if (relu) { o0.x = fmaxf(o0.x, 0.f); o0.y = fmaxf(o0.y, 0.f); }
        *reinterpret_cast<float2*>(op + lane * 2) = o0;
    }
}

// ---------------- L4 aggregation: 4 dsts per warp, 8 lanes per dst ----------
// F=8, shift=1, no relu. out = dinv[d]*(sum + dinv[d]*hraw[d>>1]) + b

__global__ __launch_bounds__(256) void k_agg8(
        const int*   __restrict__ adj,
        const int*   __restrict__ cnt,
        const float* __restrict__ hraw,
        const float* __restrict__ dinv,
        const float* __restrict__ bias,
        float*       __restrict__ out,
        int M) {
    int w    = (blockIdx.x * blockDim.x + threadIdx.x) >> 5;
    int lane = threadIdx.x & 31;
    int g    = lane >> 3;          // 0..3  dst group within warp
    int q    = lane & 7;           // 0..7  feature index
    int d    = w * 4 + g;
    if (d >= M) return;

    int n = cnt[d]; if (n > CAP) n = CAP;
    const int* ap = adj + (size_t)d * CAP;

    float acc = 0.f;
    for (int i0 = 0; i0 < n; i0 += 8) {
        int m = n - i0; if (m > 8) m = 8;
        int e = 0; float scl = 0.f;
        if (q < m) { e = ap[i0 + q]; scl = dinv[e]; }
        #pragma unroll 4
        for (int j = 0; j < m; j++) {
            int   s  = __shfl_sync(0xffffffffu, e,   g * 8 + j);
            float sc = __shfl_sync(0xffffffffu, scl, g * 8 + j);
            acc += sc * hraw[(size_t)(s >> 1) * 8 + q];
        }
    }

    float dv = dinv[d];
    float o = (acc + dv * hraw[(size_t)(d >> 1) * 8 + q]) * dv + bias[q];
    out[(size_t)d * 8 + q] = o;
}

// ---------------- host side -------------------------------------------------

extern "C" void kernel_launch(void* const* d_in, const int* in_sizes, int n_in,
                              void* d_out, int out_size) {
    const float* z   = (const float*)d_in[0];
    const int*   e1  = (const int*)d_in[1];
    const int*   ps2 = (const int*)d_in[2];
    const int*   ps1 = (const int*)d_in[3];
    const int*   ps0 = (const int*)d_in[4];
    const float* W1 = (const float*)d_in[5];
    const float* b1 = (const float*)d_in[6];
    const float* W2 = (const float*)d_in[7];
    const float* b2 = (const float*)d_in[8];
    const float* W3 = (const float*)d_in[9];
    const float* b3 = (const float*)d_in[10];
    const float* W4 = (const float*)d_in[11];
    const float* b4 = (const float*)d_in[12];

    const int h2 = 256, h1 = 128, h0 = 64;
    int N = in_sizes[0] / h2;                   // 25000
    int E1 = in_sizes[1] / 2;
    int E2 = in_sizes[2] / 2;
    int E3 = in_sizes[3] / 2;
    int E4 = in_sizes[4] / 2;

    int *cnt, *adj;
    float *dinv, *hraw, *p1, *p2;
    cudaGetSymbolAddress((void**)&cnt,  g_cnt);
    cudaGetSymbolAddress((void**)&dinv, g_dinv);
    cudaGetSymbolAddress((void**)&adj,  g_adj);
    cudaGetSymbolAddress((void**)&hraw, g_hraw);
    cudaGetSymbolAddress((void**)&p1,   g_p1);
    cudaGetSymbolAddress((void**)&p2,   g_p2);

    // node-space offsets per layer
    const int OFF1 = 0, OFF2 = 25000, OFF3 = 75000, OFF4 = 175000;

    // ---- phase 0: all graph prep in 3 nodes ----
    cudaMemsetAsync(cnt, 0, (size_t)NTOT * sizeof(int));
    int Etot = E1 + E2 + E3 + E4;
    k_build_all<<<(Etot + 255) / 256, 256>>>(e1, ps2, ps1, ps0,
                                             E1, E2, E3, E4, cnt, adj);
    k_rsqrt_all<<<(NTOT + 255) / 256, 256>>>(cnt, dinv, NTOT);

    // ---- L1: [N, 256] -> [N, 256], relu, no upsample ----
    {
        dim3 grid(h2 / 64, (N + 127) / 128);
        k_gemm_tiled<<<grid, 256>>>(z, W1, hraw, N, h2, h2);
        k_agg<256><<<(N + 7) / 8, 256>>>(adj + (size_t)OFF1 * CAP, cnt + OFF1,
                                         hraw, dinv + OFF1, b1, p1, N, 0, 1);
    }
    // ---- L2: [2N] nodes, 256 -> 128, relu, upsample folded ----
    {
        int M = 2 * N;
        dim3 grid(h1 / 64, (N + 127) / 128);
        k_gemm_tiled<<<grid, 256>>>(p1, W2, hraw, N, h2, h1);
        k_agg<128><<<(M + 7) / 8, 256>>>(adj + (size_t)OFF2 * CAP, cnt + OFF2,
                                         hraw, dinv + OFF2, b2, p2, M, 1, 1);
    }
    // ---- L3: [4N] nodes, 128 -> 64, relu ----
    {
        int M = 4 * N, Mr = 2 * N;
        dim3 grid(h0 / 64, (Mr + 127) / 128);
        k_gemm_tiled<<<grid, 256>>>(p2, W3, hraw, Mr, h1, h0);
        k_agg<64><<<(M + 7) / 8, 256>>>(adj + (size_t)OFF3 * CAP, cnt + OFF3,
                                        hraw, dinv + OFF3, b3, p1, M, 1, 1);
    }
    // ---- L4: [8N] nodes, 64 -> 8, no relu, straight to d_out ----
    {
        int M = 8 * N, Mr = 4 * N;
        int npb = 256 / 8;
        k_gemm_small<<<(Mr + npb - 1) / npb, 256>>>(p1, W4, hraw, Mr, h0, 8);
        int warps = (M + 3) / 4;
        k_agg8<<<(warps + 7) / 8, 256>>>(adj + (size_t)OFF4 * CAP, cnt + OFF4,
                                         hraw, dinv + OFF4, b4,
                                         (float*)d_out, M);
    }
}

// round 12
// speedup vs baseline: 1.0486x; 1.0486x over previous
#include <cuda_runtime.h>
#include <cstdint>

// ---------------------------------------------------------------------------
// GCN decoder: 4 x (GCNConv [+ReLU] [+upsample x2 folded into indexing])
// Phase 0: memset(cnt) -> fused build (adj for L1-L3, count-only for L4)
//          -> fused rsqrt (all 375k nodes)
// L1-L3 (F in {256,128,64}): GEMM(f32x2) -> warp-per-dst gather agg (fused fin)
// L4 (F=8): small GEMM -> red.v4 scatter -> finalize   (proven fastest at F=8)
// ---------------------------------------------------------------------------

#define MAXF 6400000
#define CAP  64
#define NTOT 375000        // 25000 + 50000 + 100000 + 200000
#define ADJN 175000        // nodes with adjacency (L1+L2+L3)

__device__ __align__(256) int   g_cnt [NTOT];
__device__ __align__(256) float g_dinv[NTOT];
__device__ __align__(256) int   g_adj [(size_t)ADJN * CAP];
__device__ __align__(256) float g_hraw[MAXF];
__device__ __align__(256) float g_acc4[1600000];   // L4 scatter accumulator
__device__ __align__(256) float g_p1  [MAXF];
__device__ __align__(256) float g_p2  [MAXF];

// ---------------- fused prep: adj build (L1-3) + count-only (L4) ------------

__global__ void k_build_all(const int* __restrict__ e1,
                            const int* __restrict__ e2,
                            const int* __restrict__ e3,
                            const int* __restrict__ e4,
                            int E1, int E2, int E3, int E4,
                            int* __restrict__ cnt,
                            int* __restrict__ adj) {
    int i = blockIdx.x * blockDim.x + threadIdx.x;
    if (i < E1) {
        int d = e1[E1 + i];
        int p = atomicAdd(&cnt[d], 1);
        if (p < CAP) adj[(size_t)d * CAP + p] = e1[i];
        return;
    }
    i -= E1;
    if (i < E2) {
        int d = 25000 + e2[E2 + i];
        int p = atomicAdd(&cnt[d], 1);
        if (p < CAP) adj[(size_t)d * CAP + p] = e2[i];
        return;
    }
    i -= E2;
    if (i < E3) {
        int d = 75000 + e3[E3 + i];
        int p = atomicAdd(&cnt[d], 1);
        if (p < CAP) adj[(size_t)d * CAP + p] = e3[i];
        return;
    }
    i -= E3;
    if (i < E4) {
        atomicAdd(&cnt[175000 + e4[E4 + i]], 1);   // count only -> RED
    }
}

__global__ void k_rsqrt_all(const int* __restrict__ cnt,
                            float* __restrict__ dinv, int M) {
    int i = blockIdx.x * blockDim.x + threadIdx.x;
    if (i < M) dinv[i] = rsqrtf((float)cnt[i] + 1.0f);
}

// ---------------- f32x2 helpers ----------------

__device__ __forceinline__ uint64_t bcast_f32x2(float x) {
    uint64_t r;
    uint32_t b = __float_as_uint(x);
    asm("mov.b64 %0, {%1, %1};" : "=l"(r) : "r"(b));
    return r;
}

__device__ __forceinline__ void fma_f32x2(uint64_t& c, uint64_t a, uint64_t b) {
    asm("fma.rn.f32x2 %0, %1, %2, %0;" : "+l"(c) : "l"(a), "l"(b));
}

__device__ __forceinline__ float2 unpack_f32x2(uint64_t p) {
    uint32_t lo, hi;
    asm("mov.b64 {%0, %1}, %2;" : "=r"(lo), "=r"(hi) : "l"(p));
    return make_float2(__uint_as_float(lo), __uint_as_float(hi));
}

// ---------------- tiled GEMM: hraw = X @ W (f32x2, 8x4 microtile) -----------

__global__ __launch_bounds__(256) void k_gemm_tiled(
        const float* __restrict__ X,
        const float* __restrict__ W,
        float* __restrict__ hraw,
        int Mr, int K, int F) {
    __shared__ float As[16][128];
    __shared__ float Bs[16][64];

    const int tid = threadIdx.x;
    const int tx  = tid & 15;
    const int ty  = tid >> 4;
    const int row0 = blockIdx.y * 128;
    const int col0 = blockIdx.x * 64;

    const int brow = tid >> 4;
    const int bc   = (tid & 15) * 4;

    uint64_t cc[4][4] = {};

    for (int k0 = 0; k0 < K; k0 += 16) {
        #pragma unroll
        for (int li = 0; li < 2; li++) {
            int i = tid + li * 256;
            int r  = i >> 2;
            int kc = (i & 3) * 4;
            int grow = row0 + r;
            float4 v = make_float4(0.f, 0.f, 0.f, 0.f);
            if (grow < Mr)
                v = *reinterpret_cast<const float4*>(
                    X + (size_t)grow * K + k0 + kc);
            As[kc + 0][r] = v.x;
            As[kc + 1][r] = v.y;
            As[kc + 2][r] = v.z;
            As[kc + 3][r] = v.w;
        }
        *reinterpret_cast<float4*>(&Bs[brow][bc]) =
            *reinterpret_cast<const float4*>(W + (size_t)(k0 + brow) * F + col0 + bc);

        __syncthreads();

        #pragma unroll
        for (int kk = 0; kk < 16; kk++) {
            const uint64_t* ap = reinterpret_cast<const uint64_t*>(&As[kk][ty * 8]);
            uint64_t a0 = ap[0], a1 = ap[1], a2 = ap[2], a3 = ap[3];
            float4 b = *reinterpret_cast<const float4*>(&Bs[kk][tx * 4]);
            uint64_t b0 = bcast_f32x2(b.x);
            uint64_t b1 = bcast_f32x2(b.y);
            uint64_t b2 = bcast_f32x2(b.z);
            uint64_t b3 = bcast_f32x2(b.w);
            fma_f32x2(cc[0][0], a0, b0); fma_f32x2(cc[0][1], a0, b1);
            fma_f32x2(cc[0][2], a0, b2); fma_f32x2(cc[0][3], a0, b3);
            fma_f32x2(cc[1][0], a1, b0); fma_f32x2(cc[1][1], a1, b1);
            fma_f32x2(cc[1][2], a1, b2); fma_f32x2(cc[1][3], a1, b3);
            fma_f32x2(cc[2][0], a2, b0); fma_f32x2(cc[2][1], a2, b1);
            fma_f32x2(cc[2][2], a2, b2); fma_f32x2(cc[2][3], a2, b3);
            fma_f32x2(cc[3][0], a3, b0); fma_f32x2(cc[3][1], a3, b1);
            fma_f32x2(cc[3][2], a3, b2); fma_f32x2(cc[3][3], a3, b3);
        }
        __syncthreads();
    }

    #pragma unroll
    for (int p = 0; p < 4; p++) {
        float2 v0 = unpack_f32x2(cc[p][0]);
        float2 v1 = unpack_f32x2(cc[p][1]);
        float2 v2 = unpack_f32x2(cc[p][2]);
        float2 v3 = unpack_f32x2(cc[p][3]);
        int rowA = row0 + ty * 8 + 2 * p;
        int rowB = rowA + 1;
        if (rowA < Mr) {
            float4 o = make_float4(v0.x, v1.x, v2.x, v3.x);
            *reinterpret_cast<float4*>(hraw + (size_t)rowA * F + col0 + tx * 4) = o;
        }
        if (rowB < Mr) {
            float4 o = make_float4(v0.y, v1.y, v2.y, v3.y);
            *reinterpret_cast<float4*>(hraw + (size_t)rowB * F + col0 + tx * 4) = o;
        }
    }
}

// ---------------- small-F GEMM (layer 4: K=64, F=8) -------------------------

__global__ void k_gemm_small(const float* __restrict__ X,
                             const float* __restrict__ W,
                             float* __restrict__ hraw,
                             int Mr, int K, int F) {
    __shared__ float Ws[512];
    for (int i = threadIdx.x; i < K * F; i += blockDim.x) Ws[i] = W[i];
    __syncthreads();

    int npb = blockDim.x / F;
    int n = blockIdx.x * npb + threadIdx.x / F;
    int f = threadIdx.x % F;
    if (n >= Mr) return;

    const float* xr = X + (size_t)n * K;
    float s = 0.f;
    #pragma unroll 8
    for (int k = 0; k < K; k++) s += xr[k] * Ws[k * F + f];

    hraw[(size_t)n * F + f] = s;
}

// ---------------- aggregation: warp per dst, MLP-unrolled edge loop ---------

template<int F>
__global__ __launch_bounds__(256) void k_agg(
        const int*   __restrict__ adj,
        const int*   __restrict__ cnt,
        const float* __restrict__ hraw,
        const float* __restrict__ dinv,
        const float* __restrict__ bias,
        float*       __restrict__ out,
        int M, int shift, int relu) {
    int w    = (blockIdx.x * blockDim.x + threadIdx.x) >> 5;
    int lane = threadIdx.x & 31;
    if (w >= M) return;
    const int d = w;
    int n = cnt[d]; if (n > CAP) n = CAP;

    constexpr int VPT = F / 32;         // 8 / 4 / 2
    float acc[VPT];
    #pragma unroll
    for (int v = 0; v < VPT; v++) acc[v] = 0.f;

    const int* ap = adj + (size_t)d * CAP;

    for (int i0 = 0; i0 < n; i0 += 32) {
        int m = n - i0; if (m > 32) m = 32;
        int e = 0; float scl = 0.f;
        if (lane < m) { e = ap[i0 + lane]; scl = dinv[e]; }

        int j = 0;
        if (F == 256) {
            for (; j + 2 <= m; j += 2) {
                int   s0 = __shfl_sync(0xffffffffu, e,   j);
                float c0 = __shfl_sync(0xffffffffu, scl, j);
                int   s1 = __shfl_sync(0xffffffffu, e,   j + 1);
                float c1 = __shfl_sync(0xffffffffu, scl, j + 1);
                const float* r0 = hraw + (size_t)(s0 >> shift) * 256;
                const float* r1 = hraw + (size_t)(s1 >> shift) * 256;
                float4 a0 = *reinterpret_cast<const float4*>(r0 + lane * 4);
                float4 b0 = *reinterpret_cast<const float4*>(r0 + 128 + lane * 4);
                float4 a1 = *reinterpret_cast<const float4*>(r1 + lane * 4);
                float4 b1 = *reinterpret_cast<const float4*>(r1 + 128 + lane * 4);
                acc[0] += c0 * a0.x; acc[1] += c0 * a0.y;
                acc[2] += c0 * a0.z; acc[3] += c0 * a0.w;
                acc[4] += c0 * b0.x; acc[5] += c0 * b0.y;
                acc[6] += c0 * b0.z; acc[7] += c0 * b0.w;
                acc[0] += c1 * a1.x; acc[1] += c1 * a1.y;
                acc[2] += c1 * a1.z; acc[3] += c1 * a1.w;
                acc[4] += c1 * b1.x; acc[5] += c1 * b1.y;
                acc[6] += c1 * b1.z; acc[7] += c1 * b1.w;
            }
        } else if (F == 128) {
            for (; j + 4 <= m; j += 4) {
                int   s0 = __shfl_sync(0xffffffffu, e,   j);
                float c0 = __shfl_sync(0xffffffffu, scl, j);
                int   s1 = __shfl_sync(0xffffffffu, e,   j + 1);
                float c1 = __shfl_sync(0xffffffffu, scl, j + 1);
                int   s2 = __shfl_sync(0xffffffffu, e,   j + 2);
                float c2 = __shfl_sync(0xffffffffu, scl, j + 2);
                int   s3 = __shfl_sync(0xffffffffu, e,   j + 3);
                float c3 = __shfl_sync(0xffffffffu, scl, j + 3);
                float4 a0 = *reinterpret_cast<const float4*>(hraw + (size_t)(s0 >> shift) * 128 + lane * 4);
                float4 a1 = *reinterpret_cast<const float4*>(hraw + (size_t)(s1 >> shift) * 128 + lane * 4);
                float4 a2 = *reinterpret_cast<const float4*>(hraw + (size_t)(s2 >> shift) * 128 + lane * 4);
                float4 a3 = *reinterpret_cast<const float4*>(hraw + (size_t)(s3 >> shift) * 128 + lane * 4);
                acc[0] += c0 * a0.x; acc[1] += c0 * a0.y; acc[2] += c0 * a0.z; acc[3] += c0 * a0.w;
                acc[0] += c1 * a1.x; acc[1] += c1 * a1.y; acc[2] += c1 * a1.z; acc[3] += c1 * a1.w;
                acc[0] += c2 * a2.x; acc[1] += c2 * a2.y; acc[2] += c2 * a2.z; acc[3] += c2 * a2.w;
                acc[0] += c3 * a3.x; acc[1] += c3 * a3.y; acc[2] += c3 * a3.z; acc[3] += c3 * a3.w;
            }
        } else {  // F == 64
            for (; j + 4 <= m; j += 4) {
                int   s0 = __shfl_sync(0xffffffffu, e,   j);
                float c0 = __shfl_sync(0xffffffffu, scl, j);
                int   s1 = __shfl_sync(0xffffffffu, e,   j + 1);
                float c1 = __shfl_sync(0xffffffffu, scl, j + 1);
                int   s2 = __shfl_sync(0xffffffffu, e,   j + 2);
                float c2 = __shfl_sync(0xffffffffu, scl, j + 2);
                int   s3 = __shfl_sync(0xffffffffu, e,   j + 3);
                float c3 = __shfl_sync(0xffffffffu, scl, j + 3);
                float2 a0 = *reinterpret_cast<const float2*>(hraw + (size_t)(s0 >> shift) * 64 + lane * 2);
                float2 a1 = *reinterpret_cast<const float2*>(hraw + (size_t)(s1 >> shift) * 64 + lane * 2);
                float2 a2 = *reinterpret_cast<const float2*>(hraw + (size_t)(s2 >> shift) * 64 + lane * 2);
                float2 a3 = *reinterpret_cast<const float2*>(hraw + (size_t)(s3 >> shift) * 64 + lane * 2);
                acc[0] += c0 * a0.x; acc[1] += c0 * a0.y;
                acc[0] += c1 * a1.x; acc[1] += c1 * a1.y;
                acc[0] += c2 * a2.x; acc[1] += c2 * a2.y;
                acc[0] += c3 * a3.x; acc[1] += c3 * a3.y;
            }
        }
        // tail
        for (; j < m; j++) {
            int   s  = __shfl_sync(0xffffffffu, e,   j);
            float sc = __shfl_sync(0xffffffffu, scl, j);
            const float* hr = hraw + (size_t)(s >> shift) * F;
            if (F == 256) {
                float4 a0 = *reinterpret_cast<const float4*>(hr + lane * 4);
                float4 b0 = *reinterpret_cast<const float4*>(hr + 128 + lane * 4);
                acc[0] += sc * a0.x; acc[1] += sc * a0.y;
                acc[2] += sc * a0.z; acc[3] += sc * a0.w;
                acc[VPT > 4 ? 4 : 0] += sc * b0.x;
                acc[VPT > 5 ? 5 : 0] += sc * b0.y;
                acc[VPT > 6 ? 6 : 0] += sc * b0.z;
                acc[VPT > 7 ? 7 : 0] += sc * b0.w;
            } else if (F == 128) {
                float4 a0 = *reinterpret_cast<const float4*>(hr + lane * 4);
                acc[0] += sc * a0.x; acc[1] += sc * a0.y;
                acc[VPT > 2 ? 2 : 0] += sc * a0.z;
                acc[VPT > 3 ? 3 : 0] += sc * a0.w;
            } else {
                float2 a0 = *reinterpret_cast<const float2*>(hr + lane * 2);
                acc[0] += sc * a0.x;
                acc[VPT > 1 ? 1 : 0] += sc * a0.y;
            }
        }
    }

    // self loop + finalize
    float dv = dinv[d];
    const float* hr = hraw + (size_t)(d >> shift) * F;
    float* op = out + (size_t)d * F;

    if (F == 256) {
        float4 h0 = *reinterpret_cast<const float4*>(hr + lane * 4);
        float4 h1 = *reinterpret_cast<const float4*>(hr + 128 + lane * 4);
        float4 b0 = *reinterpret_cast<const float4*>(bias + lane * 4);
        float4 b1 = *reinterpret_cast<const float4*>(bias + 128 + lane * 4);
        float4 o0, o1;
        o0.x = (acc[0] + dv * h0.x) * dv + b0.x;
        o0.y = (acc[1] + dv * h0.y) * dv + b0.y;
        o0.z = (acc[2] + dv * h0.z) * dv + b0.z;
        o0.w = (acc[3] + dv * h0.w) * dv + b0.w;
        o1.x = (acc[VPT > 4 ? 4 : 0] + dv * h1.x) * dv + b1.x;
        o1.y = (acc[VPT > 5 ? 5 : 0] + dv * h1.y) * dv + b1.y;
        o1.z = (acc[VPT > 6 ? 6 : 0] + dv * h1.z) * dv + b1.z;
        o1.w = (acc[VPT > 7 ? 7 : 0] + dv * h1.w) * dv + b1.w;
        if (relu) {
            o0.x = fmaxf(o0.x, 0.f); o0.y = fmaxf(o0.y, 0.f);
            o0.z = fmaxf(o0.z, 0.f); o0.w = fmaxf(o0.w, 0.f);
            o1.x = fmaxf(o1.x, 0.f); o1.y = fmaxf(o1.y, 0.f);
            o1.z = fmaxf(o1.z, 0.f); o1.w = fmaxf(o1.w, 0.f);
        }
        *reinterpret_cast<float4*>(op + lane * 4) = o0;
        *reinterpret_cast<float4*>(op + 128 + lane * 4) = o1;
    } else if (F == 128) {
        float4 h0 = *reinterpret_cast<const float4*>(hr + lane * 4);
        float4 b0 = *reinterpret_cast<const float4*>(bias + lane * 4);
        float4 o0;
        o0.x = (acc[0] + dv * h0.x) * dv + b0.x;
        o0.y = (acc[1] + dv * h0.y) * dv + b0.y;
        o0.z = (acc[VPT > 2 ? 2 : 0] + dv * h0.z) * dv + b0.z;
        o0.w = (acc[VPT > 3 ? 3 : 0] + dv * h0.w) * dv + b0.w;
        if (relu) {
            o0.x = fmaxf(o0.x, 0.f); o0.y = fmaxf(o0.y, 0.f);
            o0.z = fmaxf(o0.z, 0.f); o0.w = fmaxf(o0.w, 0.f);
        }
        *reinterpret_cast<float4*>(op + lane * 4) = o0;
    } else {  // F == 64
        float2 h0 = *reinterpret_cast<const float2*>(hr + lane * 2);
        float2 b0 = *reinterpret_cast<const float2*>(bias + lane * 2);
        float2 o0;
        o0.x = (acc[0] + dv * h0.x) * dv + b0.x;
        o0.y = (acc[VPT > 1 ? 1 : 0] + dv * h0.y) * dv + b0.y;
        if (relu) { o0.x = fmaxf(o0.x, 0.f); o0.y = fmaxf(o0.y, 0.f); }
        *reinterpret_cast<float2*>(op + lane * 2) = o0;
    }
}

// ---------------- L4 scatter + finalize (proven R9 path) --------------------

__device__ __forceinline__ void red_add_v4(float4* addr, float4 v) {
    asm volatile("red.global.add.v4.f32 [%0], {%1, %2, %3, %4};"
                 :: "l"(addr), "f"(v.x), "f"(v.y), "f"(v.z), "f"(v.w)
                 : "memory");
}

__global__ void k_scatter8(const int* __restrict__ src,
                           const int* __restrict__ dst,
                           const float* __restrict__ hraw,
                           const float* __restrict__ dinv,
                           float* __restrict__ acc,
                           int total) {             // F=8, lf4=1, shift=1
    int idx = blockIdx.x * blockDim.x + threadIdx.x;
    if (idx >= total) return;
    int e = idx >> 1;
    int c = idx & 1;
    int s = src[e];
    int d = dst[e];
    float sc = dinv[s];
    const float4* h4 = reinterpret_cast<const float4*>(hraw);
    float4 v = h4[((s >> 1) << 1) + c];
    v.x *= sc; v.y *= sc; v.z *= sc; v.w *= sc;
    red_add_v4(reinterpret_cast<float4*>(acc) + ((d << 1) + c), v);
}

__global__ void k_finalize8(const float* __restrict__ acc,
                            const float* __restrict__ hraw,
                            const float* __restrict__ dinv,
                            const float* __restrict__ bias,
                            float* __restrict__ out,
                            int total4) {           // F=8, lf4=1, shift=1
    int idx = blockIdx.x * blockDim.x + threadIdx.x;
    if (idx >= total4) return;
    int n = idx >> 1;
    int c = idx & 1;
    float dv = dinv[n];
    float4 a = reinterpret_cast<const float4*>(acc)[idx];
    float4 h = reinterpret_cast<const float4*>(hraw)[((n >> 1) << 1) + c];
    float4 b = reinterpret_cast<const float4*>(bias)[c];
    a.x = (a.x + dv * h.x) * dv + b.x;
    a.y = (a.y + dv * h.y) * dv + b.y;
    a.z = (a.z + dv * h.z) * dv + b.z;
    a.w = (a.w + dv * h.w) * dv + b.w;
    reinterpret_cast<float4*>(out)[idx] = a;
}

// ---------------- host side -------------------------------------------------

extern "C" void kernel_launch(void* const* d_in, const int* in_sizes, int n_in,
                              void* d_out, int out_size) {
    const float* z   = (const float*)d_in[0];
    const int*   e1  = (const int*)d_in[1];
    const int*   ps2 = (const int*)d_in[2];
    const int*   ps1 = (const int*)d_in[3];
    const int*   ps0 = (const int*)d_in[4];
    const float* W1 = (const float*)d_in[5];
    const float* b1 = (const float*)d_in[6];
    const float* W2 = (const float*)d_in[7];
    const float* b2 = (const float*)d_in[8];
    const float* W3 = (const float*)d_in[9];
    const float* b3 = (const float*)d_in[10];
    const float* W4 = (const float*)d_in[11];
    const float* b4 = (const float*)d_in[12];

    const int h2 = 256, h1 = 128, h0 = 64;
    int N = in_sizes[0] / h2;                   // 25000
    int E1 = in_sizes[1] / 2;
    int E2 = in_sizes[2] / 2;
    int E3 = in_sizes[3] / 2;
    int E4 = in_sizes[4] / 2;

    int *cnt, *adj;
    float *dinv, *hraw, *acc4, *p1, *p2;
    cudaGetSymbolAddress((void**)&cnt,  g_cnt);
    cudaGetSymbolAddress((void**)&dinv, g_dinv);
    cudaGetSymbolAddress((void**)&adj,  g_adj);
    cudaGetSymbolAddress((void**)&hraw, g_hraw);
    cudaGetSymbolAddress((void**)&acc4, g_acc4);
    cudaGetSymbolAddress((void**)&p1,   g_p1);
    cudaGetSymbolAddress((void**)&p2,   g_p2);

    const int OFF1 = 0, OFF2 = 25000, OFF3 = 75000, OFF4 = 175000;

    // ---- phase 0: all graph prep ----
    cudaMemsetAsync(cnt, 0, (size_t)NTOT * sizeof(int));
    cudaMemsetAsync(acc4, 0, (size_t)(8 * N) * 8 * sizeof(float));
    int Etot = E1 + E2 + E3 + E4;
    k_build_all<<<(Etot + 255) / 256, 256>>>(e1, ps2, ps1, ps0,
                                             E1, E2, E3, E4, cnt, adj);
    k_rsqrt_all<<<(NTOT + 255) / 256, 256>>>(cnt, dinv, NTOT);

    // ---- L1: [N, 256] -> [N, 256], relu, no upsample ----
    {
        dim3 grid(h2 / 64, (N + 127) / 128);
        k_gemm_tiled<<<grid, 256>>>(z, W1, hraw, N, h2, h2);
        k_agg<256><<<(N + 7) / 8, 256>>>(adj + (size_t)OFF1 * CAP, cnt + OFF1,
                                         hraw, dinv + OFF1, b1, p1, N, 0, 1);
    }
    // ---- L2: [2N] nodes, 256 -> 128, relu, upsample folded ----
    {
        int M = 2 * N;
        dim3 grid(h1 / 64, (N + 127) / 128);
        k_gemm_tiled<<<grid, 256>>>(p1, W2, hraw, N, h2, h1);
        k_agg<128><<<(M + 7) / 8, 256>>>(adj + (size_t)OFF2 * CAP, cnt + OFF2,
                                         hraw, dinv + OFF2, b2, p2, M, 1, 1);
    }
    // ---- L3: [4N] nodes, 128 -> 64, relu ----
    {
        int M = 4 * N, Mr = 2 * N;
        dim3 grid(h0 / 64, (Mr + 127) / 128);
        k_gemm_tiled<<<grid, 256>>>(p2, W3, hraw, Mr, h1, h0);
        k_agg<64><<<(M + 7) / 8, 256>>>(adj + (size_t)OFF3 * CAP, cnt + OFF3,
                                        hraw, dinv + OFF3, b3, p1, M, 1, 1);
    }
    // ---- L4: [8N] nodes, 64 -> 8, no relu, straight to d_out ----
    {
        int M = 8 * N, Mr = 4 * N;
        int npb = 256 / 8;
        k_gemm_small<<<(Mr + npb - 1) / npb, 256>>>(p1, W4, hraw, Mr, h0, 8);
        const int* srcL4 = ps0;
        const int* dstL4 = ps0 + E4;
        int totE = E4 * 2;
        k_scatter8<<<(totE + 255) / 256, 256>>>(srcL4, dstL4, hraw,
                                                dinv + OFF4, acc4, totE);
        int tot4 = M * 2;
        k_finalize8<<<(tot4 + 255) / 256, 256>>>(acc4, hraw, dinv + OFF4, b4,
                                                 (float*)d_out, tot4);
    }
}

// round 13
// speedup vs baseline: 1.1305x; 1.0781x over previous
#include <cuda_runtime.h>
#include <cuda_fp16.h>
#include <cstdint>

// ---------------------------------------------------------------------------
// GCN decoder: 4 x (GCNConv [+ReLU] [+upsample x2 folded into indexing])
// Phase 0: memset(cnt) -> fused build (adj L1-L3, count-only L4) -> rsqrt
// L1-L3: GEMM fp32 (f32x2) -> hraw stored FP16 -> warp-per-dst agg (fp32 acc)
// L4:    small GEMM fp32 -> red.v4 scatter -> finalize (all fp32)
// hraw fp16 halves the L2-roofline-bound gather traffic of the agg phase.
// ---------------------------------------------------------------------------

#define MAXF 6400000
#define CAP  64
#define NTOT 375000        // 25000 + 50000 + 100000 + 200000
#define ADJN 175000        // nodes with adjacency (L1+L2+L3)

__device__ __align__(256) int   g_cnt [NTOT];
__device__ __align__(256) float g_dinv[NTOT];
__device__ __align__(256) int   g_adj [(size_t)ADJN * CAP];
__device__ __align__(256) float g_hraw[MAXF];      // fp16 for L1-3, fp32 for L4
__device__ __align__(256) float g_acc4[1600000];   // L4 scatter accumulator
__device__ __align__(256) float g_p1  [MAXF];
__device__ __align__(256) float g_p2  [MAXF];

// ---------------- fused prep ----------------

__global__ void k_build_all(const int* __restrict__ e1,
                            const int* __restrict__ e2,
                            const int* __restrict__ e3,
                            const int* __restrict__ e4,
                            int E1, int E2, int E3, int E4,
                            int* __restrict__ cnt,
                            int* __restrict__ adj) {
    int i = blockIdx.x * blockDim.x + threadIdx.x;
    if (i < E1) {
        int d = e1[E1 + i];
        int p = atomicAdd(&cnt[d], 1);
        if (p < CAP) adj[(size_t)d * CAP + p] = e1[i];
        return;
    }
    i -= E1;
    if (i < E2) {
        int d = 25000 + e2[E2 + i];
        int p = atomicAdd(&cnt[d], 1);
        if (p < CAP) adj[(size_t)d * CAP + p] = e2[i];
        return;
    }
    i -= E2;
    if (i < E3) {
        int d = 75000 + e3[E3 + i];
        int p = atomicAdd(&cnt[d], 1);
        if (p < CAP) adj[(size_t)d * CAP + p] = e3[i];
        return;
    }
    i -= E3;
    if (i < E4) {
        atomicAdd(&cnt[175000 + e4[E4 + i]], 1);   // count only -> RED
    }
}

__global__ void k_rsqrt_all(const int* __restrict__ cnt,
                            float* __restrict__ dinv, int M) {
    int i = blockIdx.x * blockDim.x + threadIdx.x;
    if (i < M) dinv[i] = rsqrtf((float)cnt[i] + 1.0f);
}

// ---------------- f32x2 helpers ----------------

__device__ __forceinline__ uint64_t bcast_f32x2(float x) {
    uint64_t r;
    uint32_t b = __float_as_uint(x);
    asm("mov.b64 %0, {%1, %1};" : "=l"(r) : "r"(b));
    return r;
}

__device__ __forceinline__ void fma_f32x2(uint64_t& c, uint64_t a, uint64_t b) {
    asm("fma.rn.f32x2 %0, %1, %2, %0;" : "+l"(c) : "l"(a), "l"(b));
}

__device__ __forceinline__ float2 unpack_f32x2(uint64_t p) {
    uint32_t lo, hi;
    asm("mov.b64 {%0, %1}, %2;" : "=r"(lo), "=r"(hi) : "l"(p));
    return make_float2(__uint_as_float(lo), __uint_as_float(hi));
}

__device__ __forceinline__ uint32_t pack_h2(float a, float b) {
    __half2 h = __floats2half2_rn(a, b);
    return *reinterpret_cast<uint32_t*>(&h);
}

__device__ __forceinline__ void acc_h2(float* a, uint32_t p, float sc) {
    __half2 h = *reinterpret_cast<__half2*>(&p);
    float2 f = __half22float2(h);
    a[0] += sc * f.x;
    a[1] += sc * f.y;
}

__device__ __forceinline__ void cvt_h2(float* a, uint32_t p) {
    __half2 h = *reinterpret_cast<__half2*>(&p);
    float2 f = __half22float2(h);
    a[0] = f.x;
    a[1] = f.y;
}

// ---------------- tiled GEMM: hraw(FP16) = X @ W (f32x2, 8x4 microtile) -----

__global__ __launch_bounds__(256) void k_gemm_tiled(
        const float* __restrict__ X,
        const float* __restrict__ W,
        __half* __restrict__ hraw,
        int Mr, int K, int F) {
    __shared__ float As[16][128];
    __shared__ float Bs[16][64];

    const int tid = threadIdx.x;
    const int tx  = tid & 15;
    const int ty  = tid >> 4;
    const int row0 = blockIdx.y * 128;
    const int col0 = blockIdx.x * 64;

    const int brow = tid >> 4;
    const int bc   = (tid & 15) * 4;

    uint64_t cc[4][4] = {};

    for (int k0 = 0; k0 < K; k0 += 16) {
        #pragma unroll
        for (int li = 0; li < 2; li++) {
            int i = tid + li * 256;
            int r  = i >> 2;
            int kc = (i & 3) * 4;
            int grow = row0 + r;
            float4 v = make_float4(0.f, 0.f, 0.f, 0.f);
            if (grow < Mr)
                v = *reinterpret_cast<const float4*>(
                    X + (size_t)grow * K + k0 + kc);
            As[kc + 0][r] = v.x;
            As[kc + 1][r] = v.y;
            As[kc + 2][r] = v.z;
            As[kc + 3][r] = v.w;
        }
        *reinterpret_cast<float4*>(&Bs[brow][bc]) =
            *reinterpret_cast<const float4*>(W + (size_t)(k0 + brow) * F + col0 + bc);

        __syncthreads();

        #pragma unroll
        for (int kk = 0; kk < 16; kk++) {
            const uint64_t* ap = reinterpret_cast<const uint64_t*>(&As[kk][ty * 8]);
            uint64_t a0 = ap[0], a1 = ap[1], a2 = ap[2], a3 = ap[3];
            float4 b = *reinterpret_cast<const float4*>(&Bs[kk][tx * 4]);
            uint64_t b0 = bcast_f32x2(b.x);
            uint64_t b1 = bcast_f32x2(b.y);
            uint64_t b2 = bcast_f32x2(b.z);
            uint64_t b3 = bcast_f32x2(b.w);
            fma_f32x2(cc[0][0], a0, b0); fma_f32x2(cc[0][1], a0, b1);
            fma_f32x2(cc[0][2], a0, b2); fma_f32x2(cc[0][3], a0, b3);
            fma_f32x2(cc[1][0], a1, b0); fma_f32x2(cc[1][1], a1, b1);
            fma_f32x2(cc[1][2], a1, b2); fma_f32x2(cc[1][3], a1, b3);
            fma_f32x2(cc[2][0], a2, b0); fma_f32x2(cc[2][1], a2, b1);
            fma_f32x2(cc[2][2], a2, b2); fma_f32x2(cc[2][3], a2, b3);
            fma_f32x2(cc[3][0], a3, b0); fma_f32x2(cc[3][1], a3, b1);
            fma_f32x2(cc[3][2], a3, b2); fma_f32x2(cc[3][3], a3, b3);
        }
        __syncthreads();
    }

    #pragma unroll
    for (int p = 0; p < 4; p++) {
        float2 v0 = unpack_f32x2(cc[p][0]);
        float2 v1 = unpack_f32x2(cc[p][1]);
        float2 v2 = unpack_f32x2(cc[p][2]);
        float2 v3 = unpack_f32x2(cc[p][3]);
        int rowA = row0 + ty * 8 + 2 * p;
        int rowB = rowA + 1;
        if (rowA < Mr) {
            uint2 pk = make_uint2(pack_h2(v0.x, v1.x), pack_h2(v2.x, v3.x));
            *reinterpret_cast<uint2*>(hraw + (size_t)rowA * F + col0 + tx * 4) = pk;
        }
        if (rowB < Mr) {
            uint2 pk = make_uint2(pack_h2(v0.y, v1.y), pack_h2(v2.y, v3.y));
            *reinterpret_cast<uint2*>(hraw + (size_t)rowB * F + col0 + tx * 4) = pk;
        }
    }
}

// ---------------- small-F GEMM (layer 4: K=64, F=8, fp32) -------------------

__global__ void k_gemm_small(const float* __restrict__ X,
                             const float* __restrict__ W,
                             float* __restrict__ hraw,
                             int Mr, int K, int F) {
    __shared__ float Ws[512];
    for (int i = threadIdx.x; i < K * F; i += blockDim.x) Ws[i] = W[i];
    __syncthreads();

    int npb = blockDim.x / F;
    int n = blockIdx.x * npb + threadIdx.x / F;
    int f = threadIdx.x % F;
    if (n >= Mr) return;

    const float* xr = X + (size_t)n * K;
    float s = 0.f;
    #pragma unroll 8
    for (int k = 0; k < K; k++) s += xr[k] * Ws[k * F + f];

    hraw[(size_t)n * F + f] = s;
}

// ---------------- aggregation (fp16 gather, fp32 acc): warp per dst ---------
// Lane covers features [lane*VPT, lane*VPT+VPT). Edge loop unrolled x4.

template<int F>
__global__ __launch_bounds__(256) void k_agg(
        const int*   __restrict__ adj,
        const int*   __restrict__ cnt,
        const __half* __restrict__ hraw,
        const float* __restrict__ dinv,
        const float* __restrict__ bias,
        float*       __restrict__ out,
        int M, int shift, int relu) {
    int w    = (blockIdx.x * blockDim.x + threadIdx.x) >> 5;
    int lane = threadIdx.x & 31;
    if (w >= M) return;
    const int d = w;
    int n = cnt[d]; if (n > CAP) n = CAP;

    constexpr int VPT = F / 32;         // 8 / 4 / 2 halves per lane
    float acc[VPT];
    #pragma unroll
    for (int v = 0; v < VPT; v++) acc[v] = 0.f;

    const int* ap = adj + (size_t)d * CAP;
    const int lo = lane * VPT;

    for (int i0 = 0; i0 < n; i0 += 32) {
        int m = n - i0; if (m > 32) m = 32;
        int e = 0; float scl = 0.f;
        if (lane < m) { e = ap[i0 + lane]; scl = dinv[e]; }

        int j = 0;
        for (; j + 4 <= m; j += 4) {
            int   s0 = __shfl_sync(0xffffffffu, e,   j);
            float c0 = __shfl_sync(0xffffffffu, scl, j);
            int   s1 = __shfl_sync(0xffffffffu, e,   j + 1);
            float c1 = __shfl_sync(0xffffffffu, scl, j + 1);
            int   s2 = __shfl_sync(0xffffffffu, e,   j + 2);
            float c2 = __shfl_sync(0xffffffffu, scl, j + 2);
            int   s3 = __shfl_sync(0xffffffffu, e,   j + 3);
            float c3 = __shfl_sync(0xffffffffu, scl, j + 3);
            const __half* r0 = hraw + (size_t)(s0 >> shift) * F + lo;
            const __half* r1 = hraw + (size_t)(s1 >> shift) * F + lo;
            const __half* r2 = hraw + (size_t)(s2 >> shift) * F + lo;
            const __half* r3 = hraw + (size_t)(s3 >> shift) * F + lo;
            if (VPT == 8) {
                uint4 q0 = *reinterpret_cast<const uint4*>(r0);
                uint4 q1 = *reinterpret_cast<const uint4*>(r1);
                uint4 q2 = *reinterpret_cast<const uint4*>(r2);
                uint4 q3 = *reinterpret_cast<const uint4*>(r3);
                acc_h2(acc + 0, q0.x, c0); acc_h2(acc + 2, q0.y, c0);
                acc_h2(acc + 4, q0.z, c0); acc_h2(acc + 6, q0.w, c0);
                acc_h2(acc + 0, q1.x, c1); acc_h2(acc + 2, q1.y, c1);
                acc_h2(acc + 4, q1.z, c1); acc_h2(acc + 6, q1.w, c1);
                acc_h2(acc + 0, q2.x, c2); acc_h2(acc + 2, q2.y, c2);
                acc_h2(acc + 4, q2.z, c2); acc_h2(acc + 6, q2.w, c2);
                acc_h2(acc + 0, q3.x, c3); acc_h2(acc + 2, q3.y, c3);
                acc_h2(acc + 4, q3.z, c3); acc_h2(acc + 6, q3.w, c3);
            } else if (VPT == 4) {
                uint2 q0 = *reinterpret_cast<const uint2*>(r0);
                uint2 q1 = *reinterpret_cast<const uint2*>(r1);
                uint2 q2 = *reinterpret_cast<const uint2*>(r2);
                uint2 q3 = *reinterpret_cast<const uint2*>(r3);
                acc_h2(acc + 0, q0.x, c0); acc_h2(acc + 2, q0.y, c0);
                acc_h2(acc + 0, q1.x, c1); acc_h2(acc + 2, q1.y, c1);
                acc_h2(acc + 0, q2.x, c2); acc_h2(acc + 2, q2.y, c2);
                acc_h2(acc + 0, q3.x, c3); acc_h2(acc + 2, q3.y, c3);
            } else {
                uint32_t q0 = *reinterpret_cast<const uint32_t*>(r0);
                uint32_t q1 = *reinterpret_cast<const uint32_t*>(r1);
                uint32_t q2 = *reinterpret_cast<const uint32_t*>(r2);
                uint32_t q3 = *reinterpret_cast<const uint32_t*>(r3);
                acc_h2(acc, q0, c0);
                acc_h2(acc, q1, c1);
                acc_h2(acc, q2, c2);
                acc_h2(acc, q3, c3);
            }
        }
        // tail
        for (; j < m; j++) {
            int   s  = __shfl_sync(0xffffffffu, e,   j);
            float sc = __shfl_sync(0xffffffffu, scl, j);
            const __half* hr = hraw + (size_t)(s >> shift) * F + lo;
            if (VPT == 8) {
                uint4 q = *reinterpret_cast<const uint4*>(hr);
                acc_h2(acc + 0, q.x, sc); acc_h2(acc + 2, q.y, sc);
                acc_h2(acc + 4, q.z, sc); acc_h2(acc + 6, q.w, sc);
            } else if (VPT == 4) {
                uint2 q = *reinterpret_cast<const uint2*>(hr);
                acc_h2(acc + 0, q.x, sc); acc_h2(acc + 2, q.y, sc);
            } else {
                uint32_t q = *reinterpret_cast<const uint32_t*>(hr);
                acc_h2(acc, q, sc);
            }
        }
    }

    // self loop + finalize
    float dv = dinv[d];
    const __half* hr = hraw + (size_t)(d >> shift) * F + lo;
    float h[VPT];
    if (VPT == 8) {
        uint4 q = *reinterpret_cast<const uint4*>(hr);
        cvt_h2(h + 0, q.x); cvt_h2(h + 2, q.y);
        cvt_h2(h + 4, q.z); cvt_h2(h + 6, q.w);
    } else if (VPT == 4) {
        uint2 q = *reinterpret_cast<const uint2*>(hr);
        cvt_h2(h + 0, q.x); cvt_h2(h + 2, q.y);
    } else {
        uint32_t q = *reinterpret_cast<const uint32_t*>(hr);
        cvt_h2(h, q);
    }

    float o[VPT];
    #pragma unroll
    for (int v = 0; v < VPT; v++) {
        float t = (acc[v] + dv * h[v]) * dv + bias[lo + v];
        o[v] = relu ? fmaxf(t, 0.f) : t;
    }

    float* op = out + (size_t)d * F + lo;
    if (VPT == 8) {
        *reinterpret_cast<float4*>(op)     = make_float4(o[0], o[1], o[2], o[3]);
        *reinterpret_cast<float4*>(op + 4) = make_float4(o[4], o[5], o[6], o[7]);
    } else if (VPT == 4) {
        *reinterpret_cast<float4*>(op) = make_float4(o[0], o[1], o[2], o[3]);
    } else {
        *reinterpret_cast<float2*>(op) = make_float2(o[0], o[1]);
    }
}

// ---------------- L4 scatter + finalize (fp32, proven path) -----------------

__device__ __forceinline__ void red_add_v4(float4* addr, float4 v) {
    asm volatile("red.global.add.v4.f32 [%0], {%1, %2, %3, %4};"
                 :: "l"(addr), "f"(v.x), "f"(v.y), "f"(v.z), "f"(v.w)
                 : "memory");
}

__global__ void k_scatter8(const int* __restrict__ src,
                           const int* __restrict__ dst,
                           const float* __restrict__ hraw,
                           const float* __restrict__ dinv,
                           float* __restrict__ acc,
                           int total) {             // F=8, lf4=1, shift=1
    int idx = blockIdx.x * blockDim.x + threadIdx.x;
    if (idx >= total) return;
    int e = idx >> 1;
    int c = idx & 1;
    int s = src[e];
    int d = dst[e];
    float sc = dinv[s];
    const float4* h4 = reinterpret_cast<const float4*>(hraw);
    float4 v = h4[((s >> 1) << 1) + c];
    v.x *= sc; v.y *= sc; v.z *= sc; v.w *= sc;
    red_add_v4(reinterpret_cast<float4*>(acc) + ((d << 1) + c), v);
}

__global__ void k_finalize8(const float* __restrict__ acc,
                            const float* __restrict__ hraw,
                            const float* __restrict__ dinv,
                            const float* __restrict__ bias,
                            float* __restrict__ out,
                            int total4) {           // F=8, lf4=1, shift=1
    int idx = blockIdx.x * blockDim.x + threadIdx.x;
    if (idx >= total4) return;
    int n = idx >> 1;
    int c = idx & 1;
    float dv = dinv[n];
    float4 a = reinterpret_cast<const float4*>(acc)[idx];
    float4 h = reinterpret_cast<const float4*>(hraw)[((n >> 1) << 1) + c];
    float4 b = reinterpret_cast<const float4*>(bias)[c];
    a.x = (a.x + dv * h.x) * dv + b.x;
    a.y = (a.y + dv * h.y) * dv + b.y;
    a.z = (a.z + dv * h.z) * dv + b.z;
    a.w = (a.w + dv * h.w) * dv + b.w;
    reinterpret_cast<float4*>(out)[idx] = a;
}

// ---------------- host side -------------------------------------------------

extern "C" void kernel_launch(void* const* d_in, const int* in_sizes, int n_in,
                              void* d_out, int out_size) {
    const float* z   = (const float*)d_in[0];
    const int*   e1  = (const int*)d_in[1];
    const int*   ps2 = (const int*)d_in[2];
    const int*   ps1 = (const int*)d_in[3];
    const int*   ps0 = (const int*)d_in[4];
    const float* W1 = (const float*)d_in[5];
    const float* b1 = (const float*)d_in[6];
    const float* W2 = (const float*)d_in[7];
    const float* b2 = (const float*)d_in[8];
    const float* W3 = (const float*)d_in[9];
    const float* b3 = (const float*)d_in[10];
    const float* W4 = (const float*)d_in[11];
    const float* b4 = (const float*)d_in[12];

    const int h2 = 256, h1 = 128, h0 = 64;
    int N = in_sizes[0] / h2;                   // 25000
    int E1 = in_sizes[1] / 2;
    int E2 = in_sizes[2] / 2;
    int E3 = in_sizes[3] / 2;
    int E4 = in_sizes[4] / 2;

    int *cnt, *adj;
    float *dinv, *hrawf, *acc4, *p1, *p2;
    cudaGetSymbolAddress((void**)&cnt,   g_cnt);
    cudaGetSymbolAddress((void**)&dinv,  g_dinv);
    cudaGetSymbolAddress((void**)&adj,   g_adj);
    cudaGetSymbolAddress((void**)&hrawf, g_hraw);
    cudaGetSymbolAddress((void**)&acc4,  g_acc4);
    cudaGetSymbolAddress((void**)&p1,    g_p1);
    cudaGetSymbolAddress((void**)&p2,    g_p2);
    __half* hrawh = (__half*)hrawf;

    const int OFF1 = 0, OFF2 = 25000, OFF3 = 75000, OFF4 = 175000;

    // ---- phase 0: all graph prep ----
    cudaMemsetAsync(cnt, 0, (size_t)NTOT * sizeof(int));
    cudaMemsetAsync(acc4, 0, (size_t)(8 * N) * 8 * sizeof(float));
    int Etot = E1 + E2 + E3 + E4;
    k_build_all<<<(Etot + 255) / 256, 256>>>(e1, ps2, ps1, ps0,
                                             E1, E2, E3, E4, cnt, adj);
    k_rsqrt_all<<<(NTOT + 255) / 256, 256>>>(cnt, dinv, NTOT);

    // ---- L1: [N, 256] -> [N, 256], relu, no upsample ----
    {
        dim3 grid(h2 / 64, (N + 127) / 128);
        k_gemm_tiled<<<grid, 256>>>(z, W1, hrawh, N, h2, h2);
        k_agg<256><<<(N + 7) / 8, 256>>>(adj + (size_t)OFF1 * CAP, cnt + OFF1,
                                         hrawh, dinv + OFF1, b1, p1, N, 0, 1);
    }
    // ---- L2: [2N] nodes, 256 -> 128, relu, upsample folded ----
    {
        int M = 2 * N;
        dim3 grid(h1 / 64, (N + 127) / 128);
        k_gemm_tiled<<<grid, 256>>>(p1, W2, hrawh, N, h2, h1);
        k_agg<128><<<(M + 7) / 8, 256>>>(adj + (size_t)OFF2 * CAP, cnt + OFF2,
                                         hrawh, dinv + OFF2, b2, p2, M, 1, 1);
    }
    // ---- L3: [4N] nodes, 128 -> 64, relu ----
    {
        int M = 4 * N, Mr = 2 * N;
        dim3 grid(h0 / 64, (Mr + 127) / 128);
        k_gemm_tiled<<<grid, 256>>>(p2, W3, hrawh, Mr, h1, h0);
        k_agg<64><<<(M + 7) / 8, 256>>>(adj + (size_t)OFF3 * CAP, cnt + OFF3,
                                        hrawh, dinv + OFF3, b3, p1, M, 1, 1);
    }
    // ---- L4: [8N] nodes, 64 -> 8, no relu, straight to d_out (fp32) ----
    {
        int M = 8 * N, Mr = 4 * N;
        int npb = 256 / 8;
        k_gemm_small<<<(Mr + npb - 1) / npb, 256>>>(p1, W4, hrawf, Mr, h0, 8);
        const int* srcL4 = ps0;
        const int* dstL4 = ps0 + E4;
        int totE = E4 * 2;
        k_scatter8<<<(totE + 255) / 256, 256>>>(srcL4, dstL4, hrawf,
                                                dinv + OFF4, acc4, totE);
        int tot4 = M * 2;
        k_finalize8<<<(tot4 + 255) / 256, 256>>>(acc4, hrawf, dinv + OFF4, b4,
                                                 (float*)d_out, tot4);
    }
}

// round 14
// speedup vs baseline: 1.1440x; 1.0120x over previous
#include <cuda_runtime.h>
#include <cuda_fp16.h>
#include <cstdint>

// ---------------------------------------------------------------------------
// GCN decoder: 4 x (GCNConv [+ReLU] [+upsample x2 folded into indexing])
// Phase 0: memset(cnt) -> fused build (adj L1-L3, count-only L4) -> rsqrt
// L1-L3: GEMM fp32 (f32x2) -> hraw FP16 -> warp-per-dst agg:
//        HFMA2 packed accumulate (4-edge blocks) flushed into fp32 acc.
// L4:    small GEMM (fp16 out) -> red.v4.f32 scatter (fp16 gather) -> finalize
// ---------------------------------------------------------------------------

#define MAXF 6400000
#define CAP  64
#define NTOT 375000        // 25000 + 50000 + 100000 + 200000
#define ADJN 175000        // nodes with adjacency (L1+L2+L3)

__device__ __align__(256) int   g_cnt [NTOT];
__device__ __align__(256) float g_dinv[NTOT];
__device__ __align__(256) int   g_adj [(size_t)ADJN * CAP];
__device__ __align__(256) float g_hraw[MAXF];      // fp16 payload (all layers)
__device__ __align__(256) float g_acc4[1600000];   // L4 scatter accumulator
__device__ __align__(256) float g_p1  [MAXF];
__device__ __align__(256) float g_p2  [MAXF];

// ---------------- fused prep ----------------

__global__ void k_build_all(const int* __restrict__ e1,
                            const int* __restrict__ e2,
                            const int* __restrict__ e3,
                            const int* __restrict__ e4,
                            int E1, int E2, int E3, int E4,
                            int* __restrict__ cnt,
                            int* __restrict__ adj) {
    int i = blockIdx.x * blockDim.x + threadIdx.x;
    if (i < E1) {
        int d = e1[E1 + i];
        int p = atomicAdd(&cnt[d], 1);
        if (p < CAP) adj[(size_t)d * CAP + p] = e1[i];
        return;
    }
    i -= E1;
    if (i < E2) {
        int d = 25000 + e2[E2 + i];
        int p = atomicAdd(&cnt[d], 1);
        if (p < CAP) adj[(size_t)d * CAP + p] = e2[i];
        return;
    }
    i -= E2;
    if (i < E3) {
        int d = 75000 + e3[E3 + i];
        int p = atomicAdd(&cnt[d], 1);
        if (p < CAP) adj[(size_t)d * CAP + p] = e3[i];
        return;
    }
    i -= E3;
    if (i < E4) {
        atomicAdd(&cnt[175000 + e4[E4 + i]], 1);   // count only -> RED
    }
}

__global__ void k_rsqrt_all(const int* __restrict__ cnt,
                            float* __restrict__ dinv, int M) {
    int i = blockIdx.x * blockDim.x + threadIdx.x;
    if (i < M) dinv[i] = rsqrtf((float)cnt[i] + 1.0f);
}

// ---------------- f32x2 / f16x2 helpers ----------------

__device__ __forceinline__ uint64_t bcast_f32x2(float x) {
    uint64_t r;
    uint32_t b = __float_as_uint(x);
    asm("mov.b64 %0, {%1, %1};" : "=l"(r) : "r"(b));
    return r;
}

__device__ __forceinline__ void fma_f32x2(uint64_t& c, uint64_t a, uint64_t b) {
    asm("fma.rn.f32x2 %0, %1, %2, %0;" : "+l"(c) : "l"(a), "l"(b));
}

__device__ __forceinline__ float2 unpack_f32x2(uint64_t p) {
    uint32_t lo, hi;
    asm("mov.b64 {%0, %1}, %2;" : "=r"(lo), "=r"(hi) : "l"(p));
    return make_float2(__uint_as_float(lo), __uint_as_float(hi));
}

__device__ __forceinline__ uint32_t pack_h2(float a, float b) {
    __half2 h = __floats2half2_rn(a, b);
    return *reinterpret_cast<uint32_t*>(&h);
}

__device__ __forceinline__ uint32_t f2h2b(float x) {       // broadcast to half2
    __half2 h = __float2half2_rn(x);
    return *reinterpret_cast<uint32_t*>(&h);
}

__device__ __forceinline__ void hfma2(uint32_t& acc, uint32_t a, uint32_t s) {
    asm("fma.rn.f16x2 %0, %1, %2, %0;" : "+r"(acc) : "r"(a), "r"(s));
}

__device__ __forceinline__ float2 h2f2(uint32_t p) {
    __half2 h = *reinterpret_cast<__half2*>(&p);
    return __half22float2(h);
}

// ---------------- tiled GEMM: hraw(FP16) = X @ W (f32x2, 8x4 microtile) -----

__global__ __launch_bounds__(256) void k_gemm_tiled(
        const float* __restrict__ X,
        const float* __restrict__ W,
        __half* __restrict__ hraw,
        int Mr, int K, int F) {
    __shared__ float As[16][128];
    __shared__ float Bs[16][64];

    const int tid = threadIdx.x;
    const int tx  = tid & 15;
    const int ty  = tid >> 4;
    const int row0 = blockIdx.y * 128;
    const int col0 = blockIdx.x * 64;

    const int brow = tid >> 4;
    const int bc   = (tid & 15) * 4;

    uint64_t cc[4][4] = {};

    for (int k0 = 0; k0 < K; k0 += 16) {
        #pragma unroll
        for (int li = 0; li < 2; li++) {
            int i = tid + li * 256;
            int r  = i >> 2;
            int kc = (i & 3) * 4;
            int grow = row0 + r;
            float4 v = make_float4(0.f, 0.f, 0.f, 0.f);
            if (grow < Mr)
                v = *reinterpret_cast<const float4*>(
                    X + (size_t)grow * K + k0 + kc);
            As[kc + 0][r] = v.x;
            As[kc + 1][r] = v.y;
            As[kc + 2][r] = v.z;
            As[kc + 3][r] = v.w;
        }
        *reinterpret_cast<float4*>(&Bs[brow][bc]) =
            *reinterpret_cast<const float4*>(W + (size_t)(k0 + brow) * F + col0 + bc);

        __syncthreads();

        #pragma unroll
        for (int kk = 0; kk < 16; kk++) {
            const uint64_t* ap = reinterpret_cast<const uint64_t*>(&As[kk][ty * 8]);
            uint64_t a0 = ap[0], a1 = ap[1], a2 = ap[2], a3 = ap[3];
            float4 b = *reinterpret_cast<const float4*>(&Bs[kk][tx * 4]);
            uint64_t b0 = bcast_f32x2(b.x);
            uint64_t b1 = bcast_f32x2(b.y);
            uint64_t b2 = bcast_f32x2(b.z);
            uint64_t b3 = bcast_f32x2(b.w);
            fma_f32x2(cc[0][0], a0, b0); fma_f32x2(cc[0][1], a0, b1);
            fma_f32x2(cc[0][2], a0, b2); fma_f32x2(cc[0][3], a0, b3);
            fma_f32x2(cc[1][0], a1, b0); fma_f32x2(cc[1][1], a1, b1);
            fma_f32x2(cc[1][2], a1, b2); fma_f32x2(cc[1][3], a1, b3);
            fma_f32x2(cc[2][0], a2, b0); fma_f32x2(cc[2][1], a2, b1);
            fma_f32x2(cc[2][2], a2, b2); fma_f32x2(cc[2][3], a2, b3);
            fma_f32x2(cc[3][0], a3, b0); fma_f32x2(cc[3][1], a3, b1);
            fma_f32x2(cc[3][2], a3, b2); fma_f32x2(cc[3][3], a3, b3);
        }
        __syncthreads();
    }

    #pragma unroll
    for (int p = 0; p < 4; p++) {
        float2 v0 = unpack_f32x2(cc[p][0]);
        float2 v1 = unpack_f32x2(cc[p][1]);
        float2 v2 = unpack_f32x2(cc[p][2]);
        float2 v3 = unpack_f32x2(cc[p][3]);
        int rowA = row0 + ty * 8 + 2 * p;
        int rowB = rowA + 1;
        if (rowA < Mr) {
            uint2 pk = make_uint2(pack_h2(v0.x, v1.x), pack_h2(v2.x, v3.x));
            *reinterpret_cast<uint2*>(hraw + (size_t)rowA * F + col0 + tx * 4) = pk;
        }
        if (rowB < Mr) {
            uint2 pk = make_uint2(pack_h2(v0.y, v1.y), pack_h2(v2.y, v3.y));
            *reinterpret_cast<uint2*>(hraw + (size_t)rowB * F + col0 + tx * 4) = pk;
        }
    }
}

// ---------------- small-F GEMM (layer 4: K=64, F=8, fp16 out) ---------------

__global__ void k_gemm_small(const float* __restrict__ X,
                             const float* __restrict__ W,
                             __half* __restrict__ hraw,
                             int Mr, int K, int F) {
    __shared__ float Ws[512];
    for (int i = threadIdx.x; i < K * F; i += blockDim.x) Ws[i] = W[i];
    __syncthreads();

    int npb = blockDim.x / F;
    int n = blockIdx.x * npb + threadIdx.x / F;
    int f = threadIdx.x % F;
    if (n >= Mr) return;

    const float* xr = X + (size_t)n * K;
    float s = 0.f;
    #pragma unroll 8
    for (int k = 0; k < K; k++) s += xr[k] * Ws[k * F + f];

    hraw[(size_t)n * F + f] = __float2half_rn(s);
}

// ---------------- aggregation: warp per dst, HFMA2 4-edge blocks ------------
// fp16 packed accumulate over 4 edges, flushed to fp32 each block.

template<int F>
__global__ __launch_bounds__(256) void k_agg(
        const int*   __restrict__ adj,
        const int*   __restrict__ cnt,
        const __half* __restrict__ hraw,
        const float* __restrict__ dinv,
        const float* __restrict__ bias,
        float*       __restrict__ out,
        int M, int shift, int relu) {
    int w    = (blockIdx.x * blockDim.x + threadIdx.x) >> 5;
    int lane = threadIdx.x & 31;
    if (w >= M) return;
    const int d = w;
    int n = cnt[d]; if (n > CAP) n = CAP;

    constexpr int VPT = F / 32;         // 8 / 4 / 2 halves per lane
    constexpr int NH  = VPT / 2;        // 4 / 2 / 1 half2 regs
    float acc[VPT];
    #pragma unroll
    for (int v = 0; v < VPT; v++) acc[v] = 0.f;

    const int* ap = adj + (size_t)d * CAP;
    const int lo = lane * VPT;

    for (int i0 = 0; i0 < n; i0 += 32) {
        int m = n - i0; if (m > 32) m = 32;
        int e = 0; float scl = 0.f;
        if (lane < m) { e = ap[i0 + lane]; scl = dinv[e]; }

        int j = 0;
        for (; j + 4 <= m; j += 4) {
            int   s0 = __shfl_sync(0xffffffffu, e,   j);
            float c0 = __shfl_sync(0xffffffffu, scl, j);
            int   s1 = __shfl_sync(0xffffffffu, e,   j + 1);
            float c1 = __shfl_sync(0xffffffffu, scl, j + 1);
            int   s2 = __shfl_sync(0xffffffffu, e,   j + 2);
            float c2 = __shfl_sync(0xffffffffu, scl, j + 2);
            int   s3 = __shfl_sync(0xffffffffu, e,   j + 3);
            float c3 = __shfl_sync(0xffffffffu, scl, j + 3);
            uint32_t h0 = f2h2b(c0), h1 = f2h2b(c1);
            uint32_t h2c = f2h2b(c2), h3 = f2h2b(c3);
            const __half* r0 = hraw + (size_t)(s0 >> shift) * F + lo;
            const __half* r1 = hraw + (size_t)(s1 >> shift) * F + lo;
            const __half* r2 = hraw + (size_t)(s2 >> shift) * F + lo;
            const __half* r3 = hraw + (size_t)(s3 >> shift) * F + lo;

            uint32_t hacc[NH];
            #pragma unroll
            for (int k = 0; k < NH; k++) hacc[k] = 0u;

            if (VPT == 8) {
                uint4 q0 = *reinterpret_cast<const uint4*>(r0);
                uint4 q1 = *reinterpret_cast<const uint4*>(r1);
                uint4 q2 = *reinterpret_cast<const uint4*>(r2);
                uint4 q3 = *reinterpret_cast<const uint4*>(r3);
                hfma2(hacc[0], q0.x, h0); hfma2(hacc[1], q0.y, h0);
                hfma2(hacc[2], q0.z, h0); hfma2(hacc[3 < NH ? 3 : 0], q0.w, h0);
                hfma2(hacc[0], q1.x, h1); hfma2(hacc[1], q1.y, h1);
                hfma2(hacc[2], q1.z, h1); hfma2(hacc[3 < NH ? 3 : 0], q1.w, h1);
                hfma2(hacc[0], q2.x, h2c); hfma2(hacc[1], q2.y, h2c);
                hfma2(hacc[2], q2.z, h2c); hfma2(hacc[3 < NH ? 3 : 0], q2.w, h2c);
                hfma2(hacc[0], q3.x, h3); hfma2(hacc[1], q3.y, h3);
                hfma2(hacc[2], q3.z, h3); hfma2(hacc[3 < NH ? 3 : 0], q3.w, h3);
            } else if (VPT == 4) {
                uint2 q0 = *reinterpret_cast<const uint2*>(r0);
                uint2 q1 = *reinterpret_cast<const uint2*>(r1);
                uint2 q2 = *reinterpret_cast<const uint2*>(r2);
                uint2 q3 = *reinterpret_cast<const uint2*>(r3);
                hfma2(hacc[0], q0.x, h0); hfma2(hacc[1 < NH ? 1 : 0], q0.y, h0);
                hfma2(hacc[0], q1.x, h1); hfma2(hacc[1 < NH ? 1 : 0], q1.y, h1);
                hfma2(hacc[0], q2.x, h2c); hfma2(hacc[1 < NH ? 1 : 0], q2.y, h2c);
                hfma2(hacc[0], q3.x, h3); hfma2(hacc[1 < NH ? 1 : 0], q3.y, h3);
            } else {
                uint32_t q0 = *reinterpret_cast<const uint32_t*>(r0);
                uint32_t q1 = *reinterpret_cast<const uint32_t*>(r1);
                uint32_t q2 = *reinterpret_cast<const uint32_t*>(r2);
                uint32_t q3 = *reinterpret_cast<const uint32_t*>(r3);
                hfma2(hacc[0], q0, h0);
                hfma2(hacc[0], q1, h1);
                hfma2(hacc[0], q2, h2c);
                hfma2(hacc[0], q3, h3);
            }

            #pragma unroll
            for (int k = 0; k < NH; k++) {
                float2 f = h2f2(hacc[k]);
                acc[2 * k]     += f.x;
                acc[2 * k + 1] += f.y;
            }
        }
        // tail: fp32 path
        for (; j < m; j++) {
            int   s  = __shfl_sync(0xffffffffu, e,   j);
            float sc = __shfl_sync(0xffffffffu, scl, j);
            const __half* hr = hraw + (size_t)(s >> shift) * F + lo;
            #pragma unroll
            for (int k = 0; k < NH; k++) {
                uint32_t q = *reinterpret_cast<const uint32_t*>(hr + 2 * k);
                float2 f = h2f2(q);
                acc[2 * k]     += sc * f.x;
                acc[2 * k + 1] += sc * f.y;
            }
        }
    }

    // self loop + finalize (fp32)
    float dv = dinv[d];
    const __half* hr = hraw + (size_t)(d >> shift) * F + lo;
    float h[VPT];
    #pragma unroll
    for (int k = 0; k < NH; k++) {
        uint32_t q = *reinterpret_cast<const uint32_t*>(hr + 2 * k);
        float2 f = h2f2(q);
        h[2 * k] = f.x;
        h[2 * k + 1] = f.y;
    }

    float o[VPT];
    #pragma unroll
    for (int v = 0; v < VPT; v++) {
        float t = (acc[v] + dv * h[v]) * dv + bias[lo + v];
        o[v] = relu ? fmaxf(t, 0.f) : t;
    }

    float* op = out + (size_t)d * F + lo;
    if (VPT == 8) {
        *reinterpret_cast<float4*>(op)     = make_float4(o[0], o[1], o[2], o[3]);
        *reinterpret_cast<float4*>(op + 4) = make_float4(o[4], o[5], o[6], o[7]);
    } else if (VPT == 4) {
        *reinterpret_cast<float4*>(op) = make_float4(o[0], o[1], o[2], o[3]);
    } else {
        *reinterpret_cast<float2*>(op) = make_float2(o[0], o[1]);
    }
}

// ---------------- L4 scatter + finalize (fp16 gather, fp32 atomics) ---------

__device__ __forceinline__ void red_add_v4(float4* addr, float4 v) {
    asm volatile("red.global.add.v4.f32 [%0], {%1, %2, %3, %4};"
                 :: "l"(addr), "f"(v.x), "f"(v.y), "f"(v.z), "f"(v.w)
                 : "memory");
}

__global__ void k_scatter8(const int* __restrict__ src,
                           const int* __restrict__ dst,
                           const __half* __restrict__ hraw,
                           const float* __restrict__ dinv,
                           float* __restrict__ acc,
                           int E) {                 // F=8, shift=1
    int e = blockIdx.x * blockDim.x + threadIdx.x;
    if (e >= E) return;
    int s = src[e];
    int d = dst[e];
    float sc = dinv[s];
    uint4 q = *reinterpret_cast<const uint4*>(hraw + (size_t)(s >> 1) * 8);
    float2 f0 = h2f2(q.x), f1 = h2f2(q.y), f2 = h2f2(q.z), f3 = h2f2(q.w);
    float4 v0 = make_float4(sc * f0.x, sc * f0.y, sc * f1.x, sc * f1.y);
    float4 v1 = make_float4(sc * f2.x, sc * f2.y, sc * f3.x, sc * f3.y);
    float4* base = reinterpret_cast<float4*>(acc) + d * 2;
    red_add_v4(base,     v0);
    red_add_v4(base + 1, v1);
}

__global__ void k_finalize8(const float* __restrict__ acc,
                            const __half* __restrict__ hraw,
                            const float* __restrict__ dinv,
                            const float* __restrict__ bias,
                            float* __restrict__ out,
                            int total4) {           // F=8, shift=1
    int idx = blockIdx.x * blockDim.x + threadIdx.x;
    if (idx >= total4) return;
    int n = idx >> 1;
    int c = idx & 1;
    float dv = dinv[n];
    float4 a = reinterpret_cast<const float4*>(acc)[idx];
    uint2 q = *reinterpret_cast<const uint2*>(hraw + (size_t)(n >> 1) * 8 + c * 4);
    float2 f0 = h2f2(q.x), f1 = h2f2(q.y);
    float4 b = reinterpret_cast<const float4*>(bias)[c];
    a.x = (a.x + dv * f0.x) * dv + b.x;
    a.y = (a.y + dv * f0.y) * dv + b.y;
    a.z = (a.z + dv * f1.x) * dv + b.z;
    a.w = (a.w + dv * f1.y) * dv + b.w;
    reinterpret_cast<float4*>(out)[idx] = a;
}

// ---------------- host side -------------------------------------------------

extern "C" void kernel_launch(void* const* d_in, const int* in_sizes, int n_in,
                              void* d_out, int out_size) {
    const float* z   = (const float*)d_in[0];
    const int*   e1  = (const int*)d_in[1];
    const int*   ps2 = (const int*)d_in[2];
    const int*   ps1 = (const int*)d_in[3];
    const int*   ps0 = (const int*)d_in[4];
    const float* W1 = (const float*)d_in[5];
    const float* b1 = (const float*)d_in[6];
    const float* W2 = (const float*)d_in[7];
    const float* b2 = (const float*)d_in[8];
    const float* W3 = (const float*)d_in[9];
    const float* b3 = (const float*)d_in[10];
    const float* W4 = (const float*)d_in[11];
    const float* b4 = (const float*)d_in[12];

    const int h2 = 256, h1 = 128, h0 = 64;
    int N = in_sizes[0] / h2;                   // 25000
    int E1 = in_sizes[1] / 2;
    int E2 = in_sizes[2] / 2;
    int E3 = in_sizes[3] / 2;
    int E4 = in_sizes[4] / 2;

    int *cnt, *adj;
    float *dinv, *hrawf, *acc4, *p1, *p2;
    cudaGetSymbolAddress((void**)&cnt,   g_cnt);
    cudaGetSymbolAddress((void**)&dinv,  g_dinv);
    cudaGetSymbolAddress((void**)&adj,   g_adj);
    cudaGetSymbolAddress((void**)&hrawf, g_hraw);
    cudaGetSymbolAddress((void**)&acc4,  g_acc4);
    cudaGetSymbolAddress((void**)&p1,    g_p1);
    cudaGetSymbolAddress((void**)&p2,    g_p2);
    __half* hrawh = (__half*)hrawf;

    const int OFF1 = 0, OFF2 = 25000, OFF3 = 75000, OFF4 = 175000;

    // ---- phase 0: all graph prep ----
    cudaMemsetAsync(cnt, 0, (size_t)NTOT * sizeof(int));
    cudaMemsetAsync(acc4, 0, (size_t)(8 * N) * 8 * sizeof(float));
    int Etot = E1 + E2 + E3 + E4;
    k_build_all<<<(Etot + 255) / 256, 256>>>(e1, ps2, ps1, ps0,
                                             E1, E2, E3, E4, cnt, adj);
    k_rsqrt_all<<<(NTOT + 255) / 256, 256>>>(cnt, dinv, NTOT);

    // ---- L1: [N, 256] -> [N, 256], relu, no upsample ----
    {
        dim3 grid(h2 / 64, (N + 127) / 128);
        k_gemm_tiled<<<grid, 256>>>(z, W1, hrawh, N, h2, h2);
        k_agg<256><<<(N + 7) / 8, 256>>>(adj + (size_t)OFF1 * CAP, cnt + OFF1,
                                         hrawh, dinv + OFF1, b1, p1, N, 0, 1);
    }
    // ---- L2: [2N] nodes, 256 -> 128, relu, upsample folded ----
    {
        int M = 2 * N;
        dim3 grid(h1 / 64, (N + 127) / 128);
        k_gemm_tiled<<<grid, 256>>>(p1, W2, hrawh, N, h2, h1);
        k_agg<128><<<(M + 7) / 8, 256>>>(adj + (size_t)OFF2 * CAP, cnt + OFF2,
                                         hrawh, dinv + OFF2, b2, p2, M, 1, 1);
    }
    // ---- L3: [4N] nodes, 128 -> 64, relu ----
    {
        int M = 4 * N, Mr = 2 * N;
        dim3 grid(h0 / 64, (Mr + 127) / 128);
        k_gemm_tiled<<<grid, 256>>>(p2, W3, hrawh, Mr, h1, h0);
        k_agg<64><<<(M + 7) / 8, 256>>>(adj + (size_t)OFF3 * CAP, cnt + OFF3,
                                        hrawh, dinv + OFF3, b3, p1, M, 1, 1);
    }
    // ---- L4: [8N] nodes, 64 -> 8, no relu, straight to d_out ----
    {
        int M = 8 * N, Mr = 4 * N;
        int npb = 256 / 8;
        k_gemm_small<<<(Mr + npb - 1) / npb, 256>>>(p1, W4, hrawh, Mr, h0, 8);
        const int* srcL4 = ps0;
        const int* dstL4 = ps0 + E4;
        k_scatter8<<<(E4 + 255) / 256, 256>>>(srcL4, dstL4, hrawh,
                                              dinv + OFF4, acc4, E4);
        int tot4 = M * 2;
        k_finalize8<<<(tot4 + 255) / 256, 256>>>(acc4, hrawh, dinv + OFF4, b4,
                                                 (float*)d_out, tot4);
    }
}

// round 15
// speedup vs baseline: 1.5008x; 1.3118x over previous
#include <cuda_runtime.h>
#include <cuda_fp16.h>
#include <mma.h>
#include <cstdint>

using namespace nvcuda;

// ---------------------------------------------------------------------------
// GCN decoder: 4 x (GCNConv [+ReLU] [+upsample x2 folded into indexing])
// Phase 0: memset(cnt) -> fused build (adj L1-L3, count-only L4) -> rsqrt
// L1-L3: WMMA fp16 GEMM (fp32 accum) -> hraw FP16 -> warp-per-dst HFMA2 agg
// L4:    small GEMM (fp16 out) -> red.v4.f32 scatter -> finalize
// ---------------------------------------------------------------------------

#define MAXF 6400000
#define CAP  64
#define NTOT 375000        // 25000 + 50000 + 100000 + 200000
#define ADJN 175000        // nodes with adjacency (L1+L2+L3)

__device__ __align__(256) int   g_cnt [NTOT];
__device__ __align__(256) float g_dinv[NTOT];
__device__ __align__(256) int   g_adj [(size_t)ADJN * CAP];
__device__ __align__(256) float g_hraw[MAXF];      // fp16 payload (all layers)
__device__ __align__(256) float g_acc4[1600000];   // L4 scatter accumulator
__device__ __align__(256) float g_p1  [MAXF];
__device__ __align__(256) float g_p2  [MAXF];

// ---------------- fused prep ----------------

__global__ void k_build_all(const int* __restrict__ e1,
                            const int* __restrict__ e2,
                            const int* __restrict__ e3,
                            const int* __restrict__ e4,
                            int E1, int E2, int E3, int E4,
                            int* __restrict__ cnt,
                            int* __restrict__ adj) {
    int i = blockIdx.x * blockDim.x + threadIdx.x;
    if (i < E1) {
        int d = e1[E1 + i];
        int p = atomicAdd(&cnt[d], 1);
        if (p < CAP) adj[(size_t)d * CAP + p] = e1[i];
        return;
    }
    i -= E1;
    if (i < E2) {
        int d = 25000 + e2[E2 + i];
        int p = atomicAdd(&cnt[d], 1);
        if (p < CAP) adj[(size_t)d * CAP + p] = e2[i];
        return;
    }
    i -= E2;
    if (i < E3) {
        int d = 75000 + e3[E3 + i];
        int p = atomicAdd(&cnt[d], 1);
        if (p < CAP) adj[(size_t)d * CAP + p] = e3[i];
        return;
    }
    i -= E3;
    if (i < E4) {
        atomicAdd(&cnt[175000 + e4[E4 + i]], 1);   // count only -> RED
    }
}

__global__ void k_rsqrt_all(const int* __restrict__ cnt,
                            float* __restrict__ dinv, int M) {
    int i = blockIdx.x * blockDim.x + threadIdx.x;
    if (i < M) dinv[i] = rsqrtf((float)cnt[i] + 1.0f);
}

// ---------------- fp16 helpers ----------------

__device__ __forceinline__ uint32_t pack_h2(float a, float b) {
    __half2 h = __floats2half2_rn(a, b);
    return *reinterpret_cast<uint32_t*>(&h);
}

__device__ __forceinline__ uint32_t f2h2b(float x) {       // broadcast to half2
    __half2 h = __float2half2_rn(x);
    return *reinterpret_cast<uint32_t*>(&h);
}

__device__ __forceinline__ void hfma2(uint32_t& acc, uint32_t a, uint32_t s) {
    asm("fma.rn.f16x2 %0, %1, %2, %0;" : "+r"(acc) : "r"(a), "r"(s));
}

__device__ __forceinline__ float2 h2f2(uint32_t p) {
    __half2 h = *reinterpret_cast<__half2*>(&p);
    return __half22float2(h);
}

// ---------------- WMMA GEMM: hraw(FP16) = X(fp32) @ W(fp32) -----------------
// BM=64, BN in {128, 64}, BK=16, 256 threads (8 warps, 4x2 warp grid),
// warp tile 16 x (BN/2). fp16 inputs (converted in smem load), fp32 accum.

template<int BN>
__global__ __launch_bounds__(256) void k_gemm_wmma(
        const float* __restrict__ X,
        const float* __restrict__ W,
        __half* __restrict__ hraw,
        int Mr, int K, int F) {
    constexpr int BM  = 64;
    constexpr int BK  = 16;
    constexpr int WN  = BN / 2;        // warp tile cols
    constexpr int NF  = WN / 16;       // B/C frags per warp
    constexpr int LDA = BK + 8;        // 24 halves
    constexpr int LDB = BN + 8;        // halves
    constexpr int LDC = BN + 4;        // floats

    __shared__ __half Ah[BM * LDA];
    __shared__ __half Bh[BK * LDB];
    __shared__ float  Cs[BM * LDC];

    const int tid  = threadIdx.x;
    const int warp = tid >> 5;
    const int wr   = warp >> 1;        // 0..3
    const int wc   = warp & 1;         // 0..1
    const int row0 = blockIdx.y * BM;
    const int col0 = blockIdx.x * BN;

    wmma::fragment<wmma::accumulator, 16, 16, 16, float> c[NF];
    #pragma unroll
    for (int i = 0; i < NF; i++) wmma::fill_fragment(c[i], 0.0f);

    for (int k0 = 0; k0 < K; k0 += BK) {
        // A tile: 64 x 16 fp32 -> fp16 (one float4 per thread)
        {
            int r  = tid >> 2;
            int c4 = (tid & 3) * 4;
            float4 v = make_float4(0.f, 0.f, 0.f, 0.f);
            if (row0 + r < Mr)
                v = *reinterpret_cast<const float4*>(
                    X + (size_t)(row0 + r) * K + k0 + c4);
            uint2 pk = make_uint2(pack_h2(v.x, v.y), pack_h2(v.z, v.w));
            *reinterpret_cast<uint2*>(&Ah[r * LDA + c4]) = pk;
        }
        // B tile: 16 x BN fp32 -> fp16
        #pragma unroll
        for (int i = tid; i < BK * BN / 4; i += 256) {
            int r  = i / (BN / 4);
            int c4 = (i % (BN / 4)) * 4;
            float4 v = *reinterpret_cast<const float4*>(
                W + (size_t)(k0 + r) * F + col0 + c4);
            uint2 pk = make_uint2(pack_h2(v.x, v.y), pack_h2(v.z, v.w));
            *reinterpret_cast<uint2*>(&Bh[r * LDB + c4]) = pk;
        }
        __syncthreads();

        wmma::fragment<wmma::matrix_a, 16, 16, 16, __half, wmma::row_major> a;
        wmma::load_matrix_sync(a, Ah + wr * 16 * LDA, LDA);
        #pragma unroll
        for (int i = 0; i < NF; i++) {
            wmma::fragment<wmma::matrix_b, 16, 16, 16, __half, wmma::row_major> b;
            wmma::load_matrix_sync(b, Bh + wc * WN + i * 16, LDB);
            wmma::mma_sync(c[i], a, b, c[i]);
        }
        __syncthreads();
    }

    // stage accumulators to smem (fp32), then convert to fp16 global
    #pragma unroll
    for (int i = 0; i < NF; i++)
        wmma::store_matrix_sync(Cs + (wr * 16) * LDC + wc * WN + i * 16,
                                c[i], LDC, wmma::mem_row_major);
    __syncthreads();

    #pragma unroll
    for (int i = tid; i < BM * BN / 4; i += 256) {
        int r  = i / (BN / 4);
        int c4 = (i % (BN / 4)) * 4;
        if (row0 + r < Mr) {
            float4 v = *reinterpret_cast<const float4*>(&Cs[r * LDC + c4]);
            uint2 pk = make_uint2(pack_h2(v.x, v.y), pack_h2(v.z, v.w));
            *reinterpret_cast<uint2*>(
                hraw + (size_t)(row0 + r) * F + col0 + c4) = pk;
        }
    }
}

// ---------------- small-F GEMM (layer 4: K=64, F=8, fp16 out) ---------------

__global__ void k_gemm_small(const float* __restrict__ X,
                             const float* __restrict__ W,
                             __half* __restrict__ hraw,
                             int Mr, int K, int F) {
    __shared__ float Ws[512];
    for (int i = threadIdx.x; i < K * F; i += blockDim.x) Ws[i] = W[i];
    __syncthreads();

    int npb = blockDim.x / F;
    int n = blockIdx.x * npb + threadIdx.x / F;
    int f = threadIdx.x % F;
    if (n >= Mr) return;

    const float* xr = X + (size_t)n * K;
    float s = 0.f;
    #pragma unroll 8
    for (int k = 0; k < K; k++) s += xr[k] * Ws[k * F + f];

    hraw[(size_t)n * F + f] = __float2half_rn(s);
}

// ---------------- aggregation: warp per dst, HFMA2 4-edge blocks ------------

template<int F>
__global__ __launch_bounds__(256) void k_agg(
        const int*   __restrict__ adj,
        const int*   __restrict__ cnt,
        const __half* __restrict__ hraw,
        const float* __restrict__ dinv,
        const float* __restrict__ bias,
        float*       __restrict__ out,
        int M, int shift, int relu) {
    int w    = (blockIdx.x * blockDim.x + threadIdx.x) >> 5;
    int lane = threadIdx.x & 31;
    if (w >= M) return;
    const int d = w;
    int n = cnt[d]; if (n > CAP) n = CAP;

    constexpr int VPT = F / 32;         // 8 / 4 / 2 halves per lane
    constexpr int NH  = VPT / 2;        // 4 / 2 / 1 half2 regs
    float acc[VPT];
    #pragma unroll
    for (int v = 0; v < VPT; v++) acc[v] = 0.f;

    const int* ap = adj + (size_t)d * CAP;
    const int lo = lane * VPT;

    for (int i0 = 0; i0 < n; i0 += 32) {
        int m = n - i0; if (m > 32) m = 32;
        int e = 0; float scl = 0.f;
        if (lane < m) { e = ap[i0 + lane]; scl = dinv[e]; }

        int j = 0;
        for (; j + 4 <= m; j += 4) {
            int   s0 = __shfl_sync(0xffffffffu, e,   j);
            float c0 = __shfl_sync(0xffffffffu, scl, j);
            int   s1 = __shfl_sync(0xffffffffu, e,   j + 1);
            float c1 = __shfl_sync(0xffffffffu, scl, j + 1);
            int   s2 = __shfl_sync(0xffffffffu, e,   j + 2);
            float c2 = __shfl_sync(0xffffffffu, scl, j + 2);
            int   s3 = __shfl_sync(0xffffffffu, e,   j + 3);
            float c3 = __shfl_sync(0xffffffffu, scl, j + 3);
            uint32_t h0 = f2h2b(c0), h1 = f2h2b(c1);
            uint32_t h2c = f2h2b(c2), h3 = f2h2b(c3);
            const __half* r0 = hraw + (size_t)(s0 >> shift) * F + lo;
            const __half* r1 = hraw + (size_t)(s1 >> shift) * F + lo;
            const __half* r2 = hraw + (size_t)(s2 >> shift) * F + lo;
            const __half* r3 = hraw + (size_t)(s3 >> shift) * F + lo;

            uint32_t hacc[NH];
            #pragma unroll
            for (int k = 0; k < NH; k++) hacc[k] = 0u;

            if (VPT == 8) {
                uint4 q0 = *reinterpret_cast<const uint4*>(r0);
                uint4 q1 = *reinterpret_cast<const uint4*>(r1);
                uint4 q2 = *reinterpret_cast<const uint4*>(r2);
                uint4 q3 = *reinterpret_cast<const uint4*>(r3);
                hfma2(hacc[0], q0.x, h0); hfma2(hacc[1], q0.y, h0);
                hfma2(hacc[2], q0.z, h0); hfma2(hacc[3 < NH ? 3 : 0], q0.w, h0);
                hfma2(hacc[0], q1.x, h1); hfma2(hacc[1], q1.y, h1);
                hfma2(hacc[2], q1.z, h1); hfma2(hacc[3 < NH ? 3 : 0], q1.w, h1);
                hfma2(hacc[0], q2.x, h2c); hfma2(hacc[1], q2.y, h2c);
                hfma2(hacc[2], q2.z, h2c); hfma2(hacc[3 < NH ? 3 : 0], q2.w, h2c);
                hfma2(hacc[0], q3.x, h3); hfma2(hacc[1], q3.y, h3);
                hfma2(hacc[2], q3.z, h3); hfma2(hacc[3 < NH ? 3 : 0], q3.w, h3);
            } else if (VPT == 4) {
                uint2 q0 = *reinterpret_cast<const uint2*>(r0);
                uint2 q1 = *reinterpret_cast<const uint2*>(r1);
                uint2 q2 = *reinterpret_cast<const uint2*>(r2);
                uint2 q3 = *reinterpret_cast<const uint2*>(r3);
                hfma2(hacc[0], q0.x, h0); hfma2(hacc[1 < NH ? 1 : 0], q0.y, h0);
                hfma2(hacc[0], q1.x, h1); hfma2(hacc[1 < NH ? 1 : 0], q1.y, h1);
                hfma2(hacc[0], q2.x, h2c); hfma2(hacc[1 < NH ? 1 : 0], q2.y, h2c);
                hfma2(hacc[0], q3.x, h3); hfma2(hacc[1 < NH ? 1 : 0], q3.y, h3);
            } else {
                uint32_t q0 = *reinterpret_cast<const uint32_t*>(r0);
                uint32_t q1 = *reinterpret_cast<const uint32_t*>(r1);
                uint32_t q2 = *reinterpret_cast<const uint32_t*>(r2);
                uint32_t q3 = *reinterpret_cast<const uint32_t*>(r3);
                hfma2(hacc[0], q0, h0);
                hfma2(hacc[0], q1, h1);
                hfma2(hacc[0], q2, h2c);
                hfma2(hacc[0], q3, h3);
            }

            #pragma unroll
            for (int k = 0; k < NH; k++) {
                float2 f = h2f2(hacc[k]);
                acc[2 * k]     += f.x;
                acc[2 * k + 1] += f.y;
            }
        }
        // tail: fp32 path
        for (; j < m; j++) {
            int   s  = __shfl_sync(0xffffffffu, e,   j);
            float sc = __shfl_sync(0xffffffffu, scl, j);
            const __half* hr = hraw + (size_t)(s >> shift) * F + lo;
            #pragma unroll
            for (int k = 0; k < NH; k++) {
                uint32_t q = *reinterpret_cast<const uint32_t*>(hr + 2 * k);
                float2 f = h2f2(q);
                acc[2 * k]     += sc * f.x;
                acc[2 * k + 1] += sc * f.y;
            }
        }
    }

    // self loop + finalize (fp32)
    float dv = dinv[d];
    const __half* hr = hraw + (size_t)(d >> shift) * F + lo;
    float h[VPT];
    #pragma unroll
    for (int k = 0; k < NH; k++) {
        uint32_t q = *reinterpret_cast<const uint32_t*>(hr + 2 * k);
        float2 f = h2f2(q);
        h[2 * k] = f.x;
        h[2 * k + 1] = f.y;
    }

    float o[VPT];
    #pragma unroll
    for (int v = 0; v < VPT; v++) {
        float t = (acc[v] + dv * h[v]) * dv + bias[lo + v];
        o[v] = relu ? fmaxf(t, 0.f) : t;
    }

    float* op = out + (size_t)d * F + lo;
    if (VPT == 8) {
        *reinterpret_cast<float4*>(op)     = make_float4(o[0], o[1], o[2], o[3]);
        *reinterpret_cast<float4*>(op + 4) = make_float4(o[4], o[5], o[6], o[7]);
    } else if (VPT == 4) {
        *reinterpret_cast<float4*>(op) = make_float4(o[0], o[1], o[2], o[3]);
    } else {
        *reinterpret_cast<float2*>(op) = make_float2(o[0], o[1]);
    }
}

// ---------------- L4 scatter + finalize (fp16 gather, fp32 atomics) ---------

__device__ __forceinline__ void red_add_v4(float4* addr, float4 v) {
    asm volatile("red.global.add.v4.f32 [%0], {%1, %2, %3, %4};"
                 :: "l"(addr), "f"(v.x), "f"(v.y), "f"(v.z), "f"(v.w)
                 : "memory");
}

__global__ void k_scatter8(const int* __restrict__ src,
                           const int* __restrict__ dst,
                           const __half* __restrict__ hraw,
                           const float* __restrict__ dinv,
                           float* __restrict__ acc,
                           int E) {                 // F=8, shift=1
    int e = blockIdx.x * blockDim.x + threadIdx.x;
    if (e >= E) return;
    int s = src[e];
    int d = dst[e];
    float sc = dinv[s];
    uint4 q = *reinterpret_cast<const uint4*>(hraw + (size_t)(s >> 1) * 8);
    float2 f0 = h2f2(q.x), f1 = h2f2(q.y), f2 = h2f2(q.z), f3 = h2f2(q.w);
    float4 v0 = make_float4(sc * f0.x, sc * f0.y, sc * f1.x, sc * f1.y);
    float4 v1 = make_float4(sc * f2.x, sc * f2.y, sc * f3.x, sc * f3.y);
    float4* base = reinterpret_cast<float4*>(acc) + d * 2;
    red_add_v4(base,     v0);
    red_add_v4(base + 1, v1);
}

__global__ void k_finalize8(const float* __restrict__ acc,
                            const __half* __restrict__ hraw,
                            const float* __restrict__ dinv,
                            const float* __restrict__ bias,
                            float* __restrict__ out,
                            int total4) {           // F=8, shift=1
    int idx = blockIdx.x * blockDim.x + threadIdx.x;
    if (idx >= total4) return;
    int n = idx >> 1;
    int c = idx & 1;
    float dv = dinv[n];
    float4 a = reinterpret_cast<const float4*>(acc)[idx];
    uint2 q = *reinterpret_cast<const uint2*>(hraw + (size_t)(n >> 1) * 8 + c * 4);
    float2 f0 = h2f2(q.x), f1 = h2f2(q.y);
    float4 b = reinterpret_cast<const float4*>(bias)[c];
    a.x = (a.x + dv * f0.x) * dv + b.x;
    a.y = (a.y + dv * f0.y) * dv + b.y;
    a.z = (a.z + dv * f1.x) * dv + b.z;
    a.w = (a.w + dv * f1.y) * dv + b.w;
    reinterpret_cast<float4*>(out)[idx] = a;
}

// ---------------- host side -------------------------------------------------

extern "C" void kernel_launch(void* const* d_in, const int* in_sizes, int n_in,
                              void* d_out, int out_size) {
    const float* z   = (const float*)d_in[0];
    const int*   e1  = (const int*)d_in[1];
    const int*   ps2 = (const int*)d_in[2];
    const int*   ps1 = (const int*)d_in[3];
    const int*   ps0 = (const int*)d_in[4];
    const float* W1 = (const float*)d_in[5];
    const float* b1 = (const float*)d_in[6];
    const float* W2 = (const float*)d_in[7];
    const float* b2 = (const float*)d_in[8];
    const float* W3 = (const float*)d_in[9];
    const float* b3 = (const float*)d_in[10];
    const float* W4 = (const float*)d_in[11];
    const float* b4 = (const float*)d_in[12];

    const int h2 = 256, h1 = 128, h0 = 64;
    int N = in_sizes[0] / h2;                   // 25000
    int E1 = in_sizes[1] / 2;
    int E2 = in_sizes[2] / 2;
    int E3 = in_sizes[3] / 2;
    int E4 = in_sizes[4] / 2;

    int *cnt, *adj;
    float *dinv, *hrawf, *acc4, *p1, *p2;
    cudaGetSymbolAddress((void**)&cnt,   g_cnt);
    cudaGetSymbolAddress((void**)&dinv,  g_dinv);
    cudaGetSymbolAddress((void**)&adj,   g_adj);
    cudaGetSymbolAddress((void**)&hrawf, g_hraw);
    cudaGetSymbolAddress((void**)&acc4,  g_acc4);
    cudaGetSymbolAddress((void**)&p1,    g_p1);
    cudaGetSymbolAddress((void**)&p2,    g_p2);
    __half* hrawh = (__half*)hrawf;

    const int OFF1 = 0, OFF2 = 25000, OFF3 = 75000, OFF4 = 175000;

    // ---- phase 0: all graph prep ----
    cudaMemsetAsync(cnt, 0, (size_t)NTOT * sizeof(int));
    cudaMemsetAsync(acc4, 0, (size_t)(8 * N) * 8 * sizeof(float));
    int Etot = E1 + E2 + E3 + E4;
    k_build_all<<<(Etot + 255) / 256, 256>>>(e1, ps2, ps1, ps0,
                                             E1, E2, E3, E4, cnt, adj);
    k_rsqrt_all<<<(NTOT + 255) / 256, 256>>>(cnt, dinv, NTOT);

    // ---- L1: [N, 256] -> [N, 256], relu, no upsample ----
    {
        dim3 grid(h2 / 128, (N + 63) / 64);
        k_gemm_wmma<128><<<grid, 256>>>(z, W1, hrawh, N, h2, h2);
        k_agg<256><<<(N + 7) / 8, 256>>>(adj + (size_t)OFF1 * CAP, cnt + OFF1,
                                         hrawh, dinv + OFF1, b1, p1, N, 0, 1);
    }
    // ---- L2: [2N] nodes, 256 -> 128, relu, upsample folded ----
    {
        int M = 2 * N;
        dim3 grid(h1 / 128, (N + 63) / 64);
        k_gemm_wmma<128><<<grid, 256>>>(p1, W2, hrawh, N, h2, h1);
        k_agg<128><<<(M + 7) / 8, 256>>>(adj + (size_t)OFF2 * CAP, cnt + OFF2,
                                         hrawh, dinv + OFF2, b2, p2, M, 1, 1);
    }
    // ---- L3: [4N] nodes, 128 -> 64, relu ----
    {
        int M = 4 * N, Mr = 2 * N;
        dim3 grid(1, (Mr + 63) / 64);
        k_gemm_wmma<64><<<grid, 256>>>(p2, W3, hrawh, Mr, h1, h0);
        k_agg<64><<<(M + 7) / 8, 256>>>(adj + (size_t)OFF3 * CAP, cnt + OFF3,
                                        hrawh, dinv + OFF3, b3, p1, M, 1, 1);
    }
    // ---- L4: [8N] nodes, 64 -> 8, no relu, straight to d_out ----
    {
        int M = 8 * N, Mr = 4 * N;
        int npb = 256 / 8;
        k_gemm_small<<<(Mr + npb - 1) / npb, 256>>>(p1, W4, hrawh, Mr, h0, 8);
        const int* srcL4 = ps0;
        const int* dstL4 = ps0 + E4;
        k_scatter8<<<(E4 + 255) / 256, 256>>>(srcL4, dstL4, hrawh,
                                              dinv + OFF4, acc4, E4);
        int tot4 = M * 2;
        k_finalize8<<<(tot4 + 255) / 256, 256>>>(acc4, hrawh, dinv + OFF4, b4,
                                                 (float*)d_out, tot4);
    }
}

// round 16
// speedup vs baseline: 1.5550x; 1.0362x over previous
#include <cuda_runtime.h>
#include <cuda_fp16.h>
#include <mma.h>
#include <cstdint>

using namespace nvcuda;

// ---------------------------------------------------------------------------
// GCN decoder: 4 x (GCNConv [+ReLU] [+upsample x2 folded into indexing])
// Phase 0: memset(cnt) -> fused build (adj L1-L3, count-only L4) -> rsqrt
// GEMM epilogue writes hs[node] = dinv[node] * (X@W)[node>>shift] in FP16,
// expanded to node space. Agg is then a pure HADD2 gather-sum (no per-edge
// dinv gather), finalize: out = dinv[d]*(sum + hs[d]) + b.
// ---------------------------------------------------------------------------

#define MAXF 6400000
#define CAP  64
#define NTOT 375000        // 25000 + 50000 + 100000 + 200000
#define ADJN 175000        // nodes with adjacency (L1+L2+L3)

__device__ __align__(256) int   g_cnt [NTOT];
__device__ __align__(256) float g_dinv[NTOT];
__device__ __align__(256) int   g_adj [(size_t)ADJN * CAP];
__device__ __align__(256) float g_hs  [MAXF];      // fp16 scaled payload
__device__ __align__(256) float g_acc4[1600000];   // L4 scatter accumulator
__device__ __align__(256) float g_p1  [MAXF];
__device__ __align__(256) float g_p2  [MAXF];

// ---------------- fused prep ----------------

__global__ void k_build_all(const int* __restrict__ e1,
                            const int* __restrict__ e2,
                            const int* __restrict__ e3,
                            const int* __restrict__ e4,
                            int E1, int E2, int E3, int E4,
                            int* __restrict__ cnt,
                            int* __restrict__ adj) {
    int i = blockIdx.x * blockDim.x + threadIdx.x;
    if (i < E1) {
        int d = e1[E1 + i];
        int p = atomicAdd(&cnt[d], 1);
        if (p < CAP) adj[(size_t)d * CAP + p] = e1[i];
        return;
    }
    i -= E1;
    if (i < E2) {
        int d = 25000 + e2[E2 + i];
        int p = atomicAdd(&cnt[d], 1);
        if (p < CAP) adj[(size_t)d * CAP + p] = e2[i];
        return;
    }
    i -= E2;
    if (i < E3) {
        int d = 75000 + e3[E3 + i];
        int p = atomicAdd(&cnt[d], 1);
        if (p < CAP) adj[(size_t)d * CAP + p] = e3[i];
        return;
    }
    i -= E3;
    if (i < E4) {
        atomicAdd(&cnt[175000 + e4[E4 + i]], 1);   // count only -> RED
    }
}

__global__ void k_rsqrt_all(const int* __restrict__ cnt,
                            float* __restrict__ dinv, int M) {
    int i = blockIdx.x * blockDim.x + threadIdx.x;
    if (i < M) dinv[i] = rsqrtf((float)cnt[i] + 1.0f);
}

// ---------------- fp16 helpers ----------------

__device__ __forceinline__ uint32_t pack_h2(float a, float b) {
    __half2 h = __floats2half2_rn(a, b);
    return *reinterpret_cast<uint32_t*>(&h);
}

__device__ __forceinline__ float2 h2f2(uint32_t p) {
    __half2 h = *reinterpret_cast<__half2*>(&p);
    return __half22float2(h);
}

__device__ __forceinline__ uint32_t hadd2u(uint32_t a, uint32_t b) {
    __half2 r = __hadd2(*reinterpret_cast<__half2*>(&a),
                        *reinterpret_cast<__half2*>(&b));
    return *reinterpret_cast<uint32_t*>(&r);
}

// ---------------- WMMA GEMM: hs(FP16, node space) = dinv * (X @ W) ----------
// BM=64, BN in {128, 64}, BK=16, 256 threads (8 warps, 4x2 warp grid).

template<int BN>
__global__ __launch_bounds__(256) void k_gemm_wmma(
        const float* __restrict__ X,
        const float* __restrict__ W,
        __half* __restrict__ hs,
        const float* __restrict__ dinv,   // layer-local node space
        int Mr, int K, int F, int shift) {
    constexpr int BM  = 64;
    constexpr int BK  = 16;
    constexpr int WN  = BN / 2;
    constexpr int NF  = WN / 16;
    constexpr int LDA = BK + 8;
    constexpr int LDB = BN + 8;
    constexpr int LDC = BN + 4;

    __shared__ __half Ah[BM * LDA];
    __shared__ __half Bh[BK * LDB];
    __shared__ float  Cs[BM * LDC];

    const int tid  = threadIdx.x;
    const int warp = tid >> 5;
    const int wr   = warp >> 1;
    const int wc   = warp & 1;
    const int row0 = blockIdx.y * BM;
    const int col0 = blockIdx.x * BN;

    wmma::fragment<wmma::accumulator, 16, 16, 16, float> c[NF];
    #pragma unroll
    for (int i = 0; i < NF; i++) wmma::fill_fragment(c[i], 0.0f);

    for (int k0 = 0; k0 < K; k0 += BK) {
        {
            int r  = tid >> 2;
            int c4 = (tid & 3) * 4;
            float4 v = make_float4(0.f, 0.f, 0.f, 0.f);
            if (row0 + r < Mr)
                v = *reinterpret_cast<const float4*>(
                    X + (size_t)(row0 + r) * K + k0 + c4);
            uint2 pk = make_uint2(pack_h2(v.x, v.y), pack_h2(v.z, v.w));
            *reinterpret_cast<uint2*>(&Ah[r * LDA + c4]) = pk;
        }
        #pragma unroll
        for (int i = tid; i < BK * BN / 4; i += 256) {
            int r  = i / (BN / 4);
            int c4 = (i % (BN / 4)) * 4;
            float4 v = *reinterpret_cast<const float4*>(
                W + (size_t)(k0 + r) * F + col0 + c4);
            uint2 pk = make_uint2(pack_h2(v.x, v.y), pack_h2(v.z, v.w));
            *reinterpret_cast<uint2*>(&Bh[r * LDB + c4]) = pk;
        }
        __syncthreads();

        wmma::fragment<wmma::matrix_a, 16, 16, 16, __half, wmma::row_major> a;
        wmma::load_matrix_sync(a, Ah + wr * 16 * LDA, LDA);
        #pragma unroll
        for (int i = 0; i < NF; i++) {
            wmma::fragment<wmma::matrix_b, 16, 16, 16, __half, wmma::row_major> b;
            wmma::load_matrix_sync(b, Bh + wc * WN + i * 16, LDB);
            wmma::mma_sync(c[i], a, b, c[i]);
        }
        __syncthreads();
    }

    #pragma unroll
    for (int i = 0; i < NF; i++)
        wmma::store_matrix_sync(Cs + (wr * 16) * LDC + wc * WN + i * 16,
                                c[i], LDC, wmma::mem_row_major);
    __syncthreads();

    // epilogue: scale by dinv[node] and write expanded node rows
    #pragma unroll
    for (int i = tid; i < BM * BN / 4; i += 256) {
        int r  = i / (BN / 4);
        int c4 = (i % (BN / 4)) * 4;
        int graw = row0 + r;
        if (graw < Mr) {
            float4 v = *reinterpret_cast<const float4*>(&Cs[r * LDC + c4]);
            int nrep = 1 << shift;
            for (int t = 0; t < nrep; t++) {
                int node = (graw << shift) + t;
                float dv = dinv[node];
                uint2 pk = make_uint2(pack_h2(v.x * dv, v.y * dv),
                                      pack_h2(v.z * dv, v.w * dv));
                *reinterpret_cast<uint2*>(
                    hs + (size_t)node * F + col0 + c4) = pk;
            }
        }
    }
}

// ---------------- small-F GEMM (layer 4: K=64, F=8, scaled fp16 out) --------

__global__ void k_gemm_small(const float* __restrict__ X,
                             const float* __restrict__ W,
                             __half* __restrict__ hs,
                             const float* __restrict__ dinv,
                             int Mr, int K, int F) {
    __shared__ float Ws[512];
    for (int i = threadIdx.x; i < K * F; i += blockDim.x) Ws[i] = W[i];
    __syncthreads();

    int npb = blockDim.x / F;
    int n = blockIdx.x * npb + threadIdx.x / F;
    int f = threadIdx.x % F;
    if (n >= Mr) return;

    const float* xr = X + (size_t)n * K;
    float s = 0.f;
    #pragma unroll 8
    for (int k = 0; k < K; k++) s += xr[k] * Ws[k * F + f];

    int n0 = 2 * n, n1 = 2 * n + 1;                 // shift = 1 always for L4
    hs[(size_t)n0 * F + f] = __float2half_rn(s * dinv[n0]);
    hs[(size_t)n1 * F + f] = __float2half_rn(s * dinv[n1]);
}

// ---------------- aggregation: warp per dst, pure HADD2 4-edge blocks -------
// out = dinv[d] * (sum_s hs[s] + hs[d]) + b   [, relu]

template<int F>
__global__ __launch_bounds__(256) void k_agg(
        const int*   __restrict__ adj,
        const int*   __restrict__ cnt,
        const __half* __restrict__ hs,
        const float* __restrict__ dinv,
        const float* __restrict__ bias,
        float*       __restrict__ out,
        int M, int relu) {
    int w    = (blockIdx.x * blockDim.x + threadIdx.x) >> 5;
    int lane = threadIdx.x & 31;
    if (w >= M) return;
    const int d = w;
    int n = cnt[d]; if (n > CAP) n = CAP;

    constexpr int VPT = F / 32;         // 8 / 4 / 2 halves per lane
    constexpr int NH  = VPT / 2;        // 4 / 2 / 1 half2 regs
    float acc[VPT];
    #pragma unroll
    for (int v = 0; v < VPT; v++) acc[v] = 0.f;

    const int* ap = adj + (size_t)d * CAP;
    const int lo = lane * VPT;

    for (int i0 = 0; i0 < n; i0 += 32) {
        int m = n - i0; if (m > 32) m = 32;
        int e = 0;
        if (lane < m) e = ap[i0 + lane];

        int j = 0;
        for (; j + 4 <= m; j += 4) {
            int s0 = __shfl_sync(0xffffffffu, e, j);
            int s1 = __shfl_sync(0xffffffffu, e, j + 1);
            int s2 = __shfl_sync(0xffffffffu, e, j + 2);
            int s3 = __shfl_sync(0xffffffffu, e, j + 3);
            const __half* r0 = hs + (size_t)s0 * F + lo;
            const __half* r1 = hs + (size_t)s1 * F + lo;
            const __half* r2 = hs + (size_t)s2 * F + lo;
            const __half* r3 = hs + (size_t)s3 * F + lo;

            if (VPT == 8) {
                uint4 q0 = *reinterpret_cast<const uint4*>(r0);
                uint4 q1 = *reinterpret_cast<const uint4*>(r1);
                uint4 q2 = *reinterpret_cast<const uint4*>(r2);
                uint4 q3 = *reinterpret_cast<const uint4*>(r3);
                uint32_t t0 = hadd2u(hadd2u(q0.x, q1.x), hadd2u(q2.x, q3.x));
                uint32_t t1 = hadd2u(hadd2u(q0.y, q1.y), hadd2u(q2.y, q3.y));
                uint32_t t2 = hadd2u(hadd2u(q0.z, q1.z), hadd2u(q2.z, q3.z));
                uint32_t t3 = hadd2u(hadd2u(q0.w, q1.w), hadd2u(q2.w, q3.w));
                float2 f0 = h2f2(t0), f1 = h2f2(t1);
                float2 f2 = h2f2(t2), f3 = h2f2(t3);
                acc[0] += f0.x; acc[1] += f0.y;
                acc[2] += f1.x; acc[3] += f1.y;
                acc[4] += f2.x; acc[5] += f2.y;
                acc[6] += f3.x; acc[7] += f3.y;
            } else if (VPT == 4) {
                uint2 q0 = *reinterpret_cast<const uint2*>(r0);
                uint2 q1 = *reinterpret_cast<const uint2*>(r1);
                uint2 q2 = *reinterpret_cast<const uint2*>(r2);
                uint2 q3 = *reinterpret_cast<const uint2*>(r3);
                uint32_t t0 = hadd2u(hadd2u(q0.x, q1.x), hadd2u(q2.x, q3.x));
                uint32_t t1 = hadd2u(hadd2u(q0.y, q1.y), hadd2u(q2.y, q3.y));
                float2 f0 = h2f2(t0), f1 = h2f2(t1);
                acc[0] += f0.x; acc[1] += f0.y;
                acc[2] += f1.x; acc[3] += f1.y;
            } else {
                uint32_t q0 = *reinterpret_cast<const uint32_t*>(r0);
                uint32_t q1 = *reinterpret_cast<const uint32_t*>(r1);
                uint32_t q2 = *reinterpret_cast<const uint32_t*>(r2);
                uint32_t q3 = *reinterpret_cast<const uint32_t*>(r3);
                uint32_t t0 = hadd2u(hadd2u(q0, q1), hadd2u(q2, q3));
                float2 f0 = h2f2(t0);
                acc[0] += f0.x; acc[1] += f0.y;
            }
        }
        // tail: fp32 convert-add
        for (; j < m; j++) {
            int s = __shfl_sync(0xffffffffu, e, j);
            const __half* hr = hs + (size_t)s * F + lo;
            #pragma unroll
            for (int k = 0; k < NH; k++) {
                uint32_t q = *reinterpret_cast<const uint32_t*>(hr + 2 * k);
                float2 f = h2f2(q);
                acc[2 * k]     += f.x;
                acc[2 * k + 1] += f.y;
            }
        }
    }

    // self loop (hs[d] already scaled) + finalize
    float dv = dinv[d];
    const __half* hr = hs + (size_t)d * F + lo;
    float h[VPT];
    #pragma unroll
    for (int k = 0; k < NH; k++) {
        uint32_t q = *reinterpret_cast<const uint32_t*>(hr + 2 * k);
        float2 f = h2f2(q);
        h[2 * k] = f.x;
        h[2 * k + 1] = f.y;
    }

    float o[VPT];
    #pragma unroll
    for (int v = 0; v < VPT; v++) {
        float t = (acc[v] + h[v]) * dv + bias[lo + v];
        o[v] = relu ? fmaxf(t, 0.f) : t;
    }

    float* op = out + (size_t)d * F + lo;
    if (VPT == 8) {
        *reinterpret_cast<float4*>(op)     = make_float4(o[0], o[1], o[2], o[3]);
        *reinterpret_cast<float4*>(op + 4) = make_float4(o[4], o[5], o[6], o[7]);
    } else if (VPT == 4) {
        *reinterpret_cast<float4*>(op) = make_float4(o[0], o[1], o[2], o[3]);
    } else {
        *reinterpret_cast<float2*>(op) = make_float2(o[0], o[1]);
    }
}

// ---------------- L4 scatter + finalize (scaled fp16 gather) ----------------

__device__ __forceinline__ void red_add_v4(float4* addr, float4 v) {
    asm volatile("red.global.add.v4.f32 [%0], {%1, %2, %3, %4};"
                 :: "l"(addr), "f"(v.x), "f"(v.y), "f"(v.z), "f"(v.w)
                 : "memory");
}

__global__ void k_scatter8(const int* __restrict__ src,
                           const int* __restrict__ dst,
                           const __half* __restrict__ hs,
                           float* __restrict__ acc,
                           int E) {                 // F=8, node-indexed hs
    int e = blockIdx.x * blockDim.x + threadIdx.x;
    if (e >= E) return;
    int s = src[e];
    int d = dst[e];
    uint4 q = *reinterpret_cast<const uint4*>(hs + (size_t)s * 8);
    float2 f0 = h2f2(q.x), f1 = h2f2(q.y), f2 = h2f2(q.z), f3 = h2f2(q.w);
    float4 v0 = make_float4(f0.x, f0.y, f1.x, f1.y);
    float4 v1 = make_float4(f2.x, f2.y, f3.x, f3.y);
    float4* base = reinterpret_cast<float4*>(acc) + d * 2;
    red_add_v4(base,     v0);
    red_add_v4(base + 1, v1);
}

__global__ void k_finalize8(const float* __restrict__ acc,
                            const __half* __restrict__ hs,
                            const float* __restrict__ dinv,
                            const float* __restrict__ bias,
                            float* __restrict__ out,
                            int total4) {           // F=8
    int idx = blockIdx.x * blockDim.x + threadIdx.x;
    if (idx >= total4) return;
    int n = idx >> 1;
    int c = idx & 1;
    float dv = dinv[n];
    float4 a = reinterpret_cast<const float4*>(acc)[idx];
    uint2 q = *reinterpret_cast<const uint2*>(hs + (size_t)n * 8 + c * 4);
    float2 f0 = h2f2(q.x), f1 = h2f2(q.y);
    float4 b = reinterpret_cast<const float4*>(bias)[c];
    a.x = (a.x + f0.x) * dv + b.x;
    a.y = (a.y + f0.y) * dv + b.y;
    a.z = (a.z + f1.x) * dv + b.z;
    a.w = (a.w + f1.y) * dv + b.w;
    reinterpret_cast<float4*>(out)[idx] = a;
}

// ---------------- host side -------------------------------------------------

extern "C" void kernel_launch(void* const* d_in, const int* in_sizes, int n_in,
                              void* d_out, int out_size) {
    const float* z   = (const float*)d_in[0];
    const int*   e1  = (const int*)d_in[1];
    const int*   ps2 = (const int*)d_in[2];
    const int*   ps1 = (const int*)d_in[3];
    const int*   ps0 = (const int*)d_in[4];
    const float* W1 = (const float*)d_in[5];
    const float* b1 = (const float*)d_in[6];
    const float* W2 = (const float*)d_in[7];
    const float* b2 = (const float*)d_in[8];
    const float* W3 = (const float*)d_in[9];
    const float* b3 = (const float*)d_in[10];
    const float* W4 = (const float*)d_in[11];
    const float* b4 = (const float*)d_in[12];

    const int h2 = 256, h1 = 128, h0 = 64;
    int N = in_sizes[0] / h2;                   // 25000
    int E1 = in_sizes[1] / 2;
    int E2 = in_sizes[2] / 2;
    int E3 = in_sizes[3] / 2;
    int E4 = in_sizes[4] / 2;

    int *cnt, *adj;
    float *dinv, *hsf, *acc4, *p1, *p2;
    cudaGetSymbolAddress((void**)&cnt,  g_cnt);
    cudaGetSymbolAddress((void**)&dinv, g_dinv);
    cudaGetSymbolAddress((void**)&adj,  g_adj);
    cudaGetSymbolAddress((void**)&hsf,  g_hs);
    cudaGetSymbolAddress((void**)&acc4, g_acc4);
    cudaGetSymbolAddress((void**)&p1,   g_p1);
    cudaGetSymbolAddress((void**)&p2,   g_p2);
    __half* hs = (__half*)hsf;

    const int OFF1 = 0, OFF2 = 25000, OFF3 = 75000, OFF4 = 175000;

    // ---- phase 0: all graph prep ----
    cudaMemsetAsync(cnt, 0, (size_t)NTOT * sizeof(int));
    cudaMemsetAsync(acc4, 0, (size_t)(8 * N) * 8 * sizeof(float));
    int Etot = E1 + E2 + E3 + E4;
    k_build_all<<<(Etot + 255) / 256, 256>>>(e1, ps2, ps1, ps0,
                                             E1, E2, E3, E4, cnt, adj);
    k_rsqrt_all<<<(NTOT + 255) / 256, 256>>>(cnt, dinv, NTOT);

    // ---- L1: [N, 256] -> [N, 256], relu, no upsample ----
    {
        dim3 grid(h2 / 128, (N + 63) / 64);
        k_gemm_wmma<128><<<grid, 256>>>(z, W1, hs, dinv + OFF1, N, h2, h2, 0);
        k_agg<256><<<(N + 7) / 8, 256>>>(adj + (size_t)OFF1 * CAP, cnt + OFF1,
                                         hs, dinv + OFF1, b1, p1, N, 1);
    }
    // ---- L2: [2N] nodes, 256 -> 128, relu, upsample folded ----
    {
        int M = 2 * N;
        dim3 grid(h1 / 128, (N + 63) / 64);
        k_gemm_wmma<128><<<grid, 256>>>(p1, W2, hs, dinv + OFF2, N, h2, h1, 1);
        k_agg<128><<<(M + 7) / 8, 256>>>(adj + (size_t)OFF2 * CAP, cnt + OFF2,
                                         hs, dinv + OFF2, b2, p2, M, 1);
    }
    // ---- L3: [4N] nodes, 128 -> 64, relu ----
    {
        int M = 4 * N, Mr = 2 * N;
        dim3 grid(1, (Mr + 63) / 64);
        k_gemm_wmma<64><<<grid, 256>>>(p2, W3, hs, dinv + OFF3, Mr, h1, h0, 1);
        k_agg<64><<<(M + 7) / 8, 256>>>(adj + (size_t)OFF3 * CAP, cnt + OFF3,
                                        hs, dinv + OFF3, b3, p1, M, 1);
    }
    // ---- L4: [8N] nodes, 64 -> 8, no relu, straight to d_out ----
    {
        int M = 8 * N, Mr = 4 * N;
        int npb = 256 / 8;
        k_gemm_small<<<(Mr + npb - 1) / npb, 256>>>(p1, W4, hs, dinv + OFF4,
                                                    Mr, h0, 8);
        const int* srcL4 = ps0;
        const int* dstL4 = ps0 + E4;
        k_scatter8<<<(E4 + 255) / 256, 256>>>(srcL4, dstL4, hs, acc4, E4);
        int tot4 = M * 2;
        k_finalize8<<<(tot4 + 255) / 256, 256>>>(acc4, hs, dinv + OFF4, b4,
                                                 (float*)d_out, tot4);
    }
}

// round 17
// speedup vs baseline: 1.6872x; 1.0850x over previous
#include <cuda_runtime.h>
#include <cuda_fp16.h>
#include <mma.h>
#include <cstdint>

using namespace nvcuda;

// ---------------------------------------------------------------------------
// GCN decoder: 4 x (GCNConv [+ReLU] [+upsample x2 folded into indexing])
// Phase 0: memset(cnt) -> fused build (adj L1-L3, count L4, zero acc4)
// dinv is computed inline everywhere as rsqrtf(cnt+1) (no array, no kernel).
// GEMM epilogue writes hs[node] = dinv[node] * (X@W)[node>>shift] in FP16.
// Agg: pure HADD2 gather-sum; finalize: out = dinv[d]*(sum + hs[d]) + b.
// L4: smem-staged small GEMM -> red.v4 scatter -> finalize.
// ---------------------------------------------------------------------------

#define MAXF 6400000
#define CAP  64
#define NTOT 375000        // 25000 + 50000 + 100000 + 200000
#define ADJN 175000        // nodes with adjacency (L1+L2+L3)
#define NACC4 1600000      // L4 accumulator floats (200000 * 8)

__device__ __align__(256) int   g_cnt [NTOT];
__device__ __align__(256) int   g_adj [(size_t)ADJN * CAP];
__device__ __align__(256) float g_hs  [MAXF];      // fp16 scaled payload
__device__ __align__(256) float g_acc4[NACC4];     // L4 scatter accumulator
__device__ __align__(256) float g_p1  [MAXF];
__device__ __align__(256) float g_p2  [MAXF];

// ---------------- fused prep: adj build + L4 count + acc4 zero --------------

__global__ void k_build_all(const int* __restrict__ e1,
                            const int* __restrict__ e2,
                            const int* __restrict__ e3,
                            const int* __restrict__ e4,
                            int E1, int E2, int E3, int E4,
                            int* __restrict__ cnt,
                            int* __restrict__ adj,
                            float4* __restrict__ acc4) {
    int i = blockIdx.x * blockDim.x + threadIdx.x;
    if (i < NACC4 / 4)
        acc4[i] = make_float4(0.f, 0.f, 0.f, 0.f);
    if (i < E1) {
        int d = e1[E1 + i];
        int p = atomicAdd(&cnt[d], 1);
        if (p < CAP) adj[(size_t)d * CAP + p] = e1[i];
        return;
    }
    i -= E1;
    if (i < E2) {
        int d = 25000 + e2[E2 + i];
        int p = atomicAdd(&cnt[d], 1);
        if (p < CAP) adj[(size_t)d * CAP + p] = e2[i];
        return;
    }
    i -= E2;
    if (i < E3) {
        int d = 75000 + e3[E3 + i];
        int p = atomicAdd(&cnt[d], 1);
        if (p < CAP) adj[(size_t)d * CAP + p] = e3[i];
        return;
    }
    i -= E3;
    if (i < E4) {
        atomicAdd(&cnt[175000 + e4[E4 + i]], 1);   // count only -> RED
    }
}

// ---------------- fp16 helpers ----------------

__device__ __forceinline__ uint32_t pack_h2(float a, float b) {
    __half2 h = __floats2half2_rn(a, b);
    return *reinterpret_cast<uint32_t*>(&h);
}

__device__ __forceinline__ float2 h2f2(uint32_t p) {
    __half2 h = *reinterpret_cast<__half2*>(&p);
    return __half22float2(h);
}

__device__ __forceinline__ uint32_t hadd2u(uint32_t a, uint32_t b) {
    __half2 r = __hadd2(*reinterpret_cast<__half2*>(&a),
                        *reinterpret_cast<__half2*>(&b));
    return *reinterpret_cast<uint32_t*>(&r);
}

__device__ __forceinline__ float dinv_of(const int* cnt, int node) {
    return rsqrtf((float)cnt[node] + 1.0f);
}

// ---------------- WMMA GEMM: hs(FP16, node space) = dinv * (X @ W) ----------

template<int BN>
__global__ __launch_bounds__(256) void k_gemm_wmma(
        const float* __restrict__ X,
        const float* __restrict__ W,
        __half* __restrict__ hs,
        const int* __restrict__ cnt,      // layer-local node space
        int Mr, int K, int F, int shift) {
    constexpr int BM  = 64;
    constexpr int BK  = 16;
    constexpr int WN  = BN / 2;
    constexpr int NF  = WN / 16;
    constexpr int LDA = BK + 8;
    constexpr int LDB = BN + 8;
    constexpr int LDC = BN + 4;

    __shared__ __half Ah[BM * LDA];
    __shared__ __half Bh[BK * LDB];
    __shared__ float  Cs[BM * LDC];

    const int tid  = threadIdx.x;
    const int warp = tid >> 5;
    const int wr   = warp >> 1;
    const int wc   = warp & 1;
    const int row0 = blockIdx.y * BM;
    const int col0 = blockIdx.x * BN;

    wmma::fragment<wmma::accumulator, 16, 16, 16, float> c[NF];
    #pragma unroll
    for (int i = 0; i < NF; i++) wmma::fill_fragment(c[i], 0.0f);

    for (int k0 = 0; k0 < K; k0 += BK) {
        {
            int r  = tid >> 2;
            int c4 = (tid & 3) * 4;
            float4 v = make_float4(0.f, 0.f, 0.f, 0.f);
            if (row0 + r < Mr)
                v = *reinterpret_cast<const float4*>(
                    X + (size_t)(row0 + r) * K + k0 + c4);
            uint2 pk = make_uint2(pack_h2(v.x, v.y), pack_h2(v.z, v.w));
            *reinterpret_cast<uint2*>(&Ah[r * LDA + c4]) = pk;
        }
        #pragma unroll
        for (int i = tid; i < BK * BN / 4; i += 256) {
            int r  = i / (BN / 4);
            int c4 = (i % (BN / 4)) * 4;
            float4 v = *reinterpret_cast<const float4*>(
                W + (size_t)(k0 + r) * F + col0 + c4);
            uint2 pk = make_uint2(pack_h2(v.x, v.y), pack_h2(v.z, v.w));
            *reinterpret_cast<uint2*>(&Bh[r * LDB + c4]) = pk;
        }
        __syncthreads();

        wmma::fragment<wmma::matrix_a, 16, 16, 16, __half, wmma::row_major> a;
        wmma::load_matrix_sync(a, Ah + wr * 16 * LDA, LDA);
        #pragma unroll
        for (int i = 0; i < NF; i++) {
            wmma::fragment<wmma::matrix_b, 16, 16, 16, __half, wmma::row_major> b;
            wmma::load_matrix_sync(b, Bh + wc * WN + i * 16, LDB);
            wmma::mma_sync(c[i], a, b, c[i]);
        }
        __syncthreads();
    }

    #pragma unroll
    for (int i = 0; i < NF; i++)
        wmma::store_matrix_sync(Cs + (wr * 16) * LDC + wc * WN + i * 16,
                                c[i], LDC, wmma::mem_row_major);
    __syncthreads();

    // epilogue: scale by rsqrt(cnt+1) and write expanded node rows
    #pragma unroll
    for (int i = tid; i < BM * BN / 4; i += 256) {
        int r  = i / (BN / 4);
        int c4 = (i % (BN / 4)) * 4;
        int graw = row0 + r;
        if (graw < Mr) {
            float4 v = *reinterpret_cast<const float4*>(&Cs[r * LDC + c4]);
            int nrep = 1 << shift;
            for (int t = 0; t < nrep; t++) {
                int node = (graw << shift) + t;
                float dv = dinv_of(cnt, node);
                uint2 pk = make_uint2(pack_h2(v.x * dv, v.y * dv),
                                      pack_h2(v.z * dv, v.w * dv));
                *reinterpret_cast<uint2*>(
                    hs + (size_t)node * F + col0 + c4) = pk;
            }
        }
    }
}

// ---------------- small-F GEMM (layer 4: K=64, F=8, smem-staged X) ----------
// 256 threads = 32 raw nodes per block (8 lanes per node).

__global__ __launch_bounds__(256) void k_gemm_small(
        const float* __restrict__ X,
        const float* __restrict__ W,
        __half* __restrict__ hs,
        const int* __restrict__ cnt,
        int Mr) {
    constexpr int K = 64, F = 8;
    __shared__ float Ws[K * F];                   // 512
    __shared__ float Xs[32][K + 4];               // 32 rows, padded

    for (int i = threadIdx.x; i < K * F; i += 256) Ws[i] = W[i];

    int nb0 = blockIdx.x * 32;                    // first raw node of block
    // cooperative stage: 32 rows x 16 float4 = 512 float4
    for (int i = threadIdx.x; i < 32 * (K / 4); i += 256) {
        int r  = i / (K / 4);
        int c4 = (i % (K / 4)) * 4;
        if (nb0 + r < Mr) {
            float4 v = *reinterpret_cast<const float4*>(
                X + (size_t)(nb0 + r) * K + c4);
            Xs[r][c4]     = v.x;
            Xs[r][c4 + 1] = v.y;
            Xs[r][c4 + 2] = v.z;
            Xs[r][c4 + 3] = v.w;
        }
    }
    __syncthreads();

    int rl = threadIdx.x >> 3;                    // 0..31 local node
    int f  = threadIdx.x & 7;
    int n  = nb0 + rl;
    if (n >= Mr) return;

    const float* xr = Xs[rl];
    float s = 0.f;
    #pragma unroll 16
    for (int k = 0; k < K; k++) s += xr[k] * Ws[k * F + f];

    int n0 = 2 * n, n1 = 2 * n + 1;               // shift = 1 for L4
    hs[(size_t)n0 * F + f] = __float2half_rn(s * dinv_of(cnt, n0));
    hs[(size_t)n1 * F + f] = __float2half_rn(s * dinv_of(cnt, n1));
}

// ---------------- aggregation: warp per dst, pure HADD2 4-edge blocks -------

template<int F>
__global__ __launch_bounds__(256) void k_agg(
        const int*   __restrict__ adj,
        const int*   __restrict__ cnt,
        const __half* __restrict__ hs,
        const float* __restrict__ bias,
        float*       __restrict__ out,
        int M, int relu) {
    int w    = (blockIdx.x * blockDim.x + threadIdx.x) >> 5;
    int lane = threadIdx.x & 31;
    if (w >= M) return;
    const int d = w;
    int n0 = cnt[d];
    int n = n0 > CAP ? CAP : n0;

    constexpr int VPT = F / 32;
    constexpr int NH  = VPT / 2;
    float acc[VPT];
    #pragma unroll
    for (int v = 0; v < VPT; v++) acc[v] = 0.f;

    const int* ap = adj + (size_t)d * CAP;
    const int lo = lane * VPT;

    for (int i0 = 0; i0 < n; i0 += 32) {
        int m = n - i0; if (m > 32) m = 32;
        int e = 0;
        if (lane < m) e = ap[i0 + lane];

        int j = 0;
        for (; j + 4 <= m; j += 4) {
            int s0 = __shfl_sync(0xffffffffu, e, j);
            int s1 = __shfl_sync(0xffffffffu, e, j + 1);
            int s2 = __shfl_sync(0xffffffffu, e, j + 2);
            int s3 = __shfl_sync(0xffffffffu, e, j + 3);
            const __half* r0 = hs + (size_t)s0 * F + lo;
            const __half* r1 = hs + (size_t)s1 * F + lo;
            const __half* r2 = hs + (size_t)s2 * F + lo;
            const __half* r3 = hs + (size_t)s3 * F + lo;

            if (VPT == 8) {
                uint4 q0 = *reinterpret_cast<const uint4*>(r0);
                uint4 q1 = *reinterpret_cast<const uint4*>(r1);
                uint4 q2 = *reinterpret_cast<const uint4*>(r2);
                uint4 q3 = *reinterpret_cast<const uint4*>(r3);
                uint32_t t0 = hadd2u(hadd2u(q0.x, q1.x), hadd2u(q2.x, q3.x));
                uint32_t t1 = hadd2u(hadd2u(q0.y, q1.y), hadd2u(q2.y, q3.y));
                uint32_t t2 = hadd2u(hadd2u(q0.z, q1.z), hadd2u(q2.z, q3.z));
                uint32_t t3 = hadd2u(hadd2u(q0.w, q1.w), hadd2u(q2.w, q3.w));
                float2 f0 = h2f2(t0), f1 = h2f2(t1);
                float2 f2 = h2f2(t2), f3 = h2f2(t3);
                acc[0] += f0.x; acc[1] += f0.y;
                acc[2] += f1.x; acc[3] += f1.y;
                acc[4] += f2.x; acc[5] += f2.y;
                acc[6] += f3.x; acc[7] += f3.y;
            } else if (VPT == 4) {
                uint2 q0 = *reinterpret_cast<const uint2*>(r0);
                uint2 q1 = *reinterpret_cast<const uint2*>(r1);
                uint2 q2 = *reinterpret_cast<const uint2*>(r2);
                uint2 q3 = *reinterpret_cast<const uint2*>(r3);
                uint32_t t0 = hadd2u(hadd2u(q0.x, q1.x), hadd2u(q2.x, q3.x));
                uint32_t t1 = hadd2u(hadd2u(q0.y, q1.y), hadd2u(q2.y, q3.y));
                float2 f0 = h2f2(t0), f1 = h2f2(t1);
                acc[0] += f0.x; acc[1] += f0.y;
                acc[2] += f1.x; acc[3] += f1.y;
            } else {
                uint32_t q0 = *reinterpret_cast<const uint32_t*>(r0);
                uint32_t q1 = *reinterpret_cast<const uint32_t*>(r1);
                uint32_t q2 = *reinterpret_cast<const uint32_t*>(r2);
                uint32_t q3 = *reinterpret_cast<const uint32_t*>(r3);
                uint32_t t0 = hadd2u(hadd2u(q0, q1), hadd2u(q2, q3));
                float2 f0 = h2f2(t0);
                acc[0] += f0.x; acc[1] += f0.y;
            }
        }
        for (; j < m; j++) {
            int s = __shfl_sync(0xffffffffu, e, j);
            const __half* hr = hs + (size_t)s * F + lo;
            #pragma unroll
            for (int k = 0; k < NH; k++) {
                uint32_t q = *reinterpret_cast<const uint32_t*>(hr + 2 * k);
                float2 f = h2f2(q);
                acc[2 * k]     += f.x;
                acc[2 * k + 1] += f.y;
            }
        }
    }

    // self loop (hs[d] already scaled) + finalize
    float dv = rsqrtf((float)n0 + 1.0f);
    const __half* hr = hs + (size_t)d * F + lo;
    float h[VPT];
    #pragma unroll
    for (int k = 0; k < NH; k++) {
        uint32_t q = *reinterpret_cast<const uint32_t*>(hr + 2 * k);
        float2 f = h2f2(q);
        h[2 * k] = f.x;
        h[2 * k + 1] = f.y;
    }

    float o[VPT];
    #pragma unroll
    for (int v = 0; v < VPT; v++) {
        float t = (acc[v] + h[v]) * dv + bias[lo + v];
        o[v] = relu ? fmaxf(t, 0.f) : t;
    }

    float* op = out + (size_t)d * F + lo;
    if (VPT == 8) {
        *reinterpret_cast<float4*>(op)     = make_float4(o[0], o[1], o[2], o[3]);
        *reinterpret_cast<float4*>(op + 4) = make_float4(o[4], o[5], o[6], o[7]);
    } else if (VPT == 4) {
        *reinterpret_cast<float4*>(op) = make_float4(o[0], o[1], o[2], o[3]);
    } else {
        *reinterpret_cast<float2*>(op) = make_float2(o[0], o[1]);
    }
}

// ---------------- L4 scatter + finalize (scaled fp16 gather) ----------------

__device__ __forceinline__ void red_add_v4(float4* addr, float4 v) {
    asm volatile("red.global.add.v4.f32 [%0], {%1, %2, %3, %4};"
                 :: "l"(addr), "f"(v.x), "f"(v.y), "f"(v.z), "f"(v.w)
                 : "memory");
}

__global__ void k_scatter8(const int* __restrict__ src,
                           const int* __restrict__ dst,
                           const __half* __restrict__ hs,
                           float* __restrict__ acc,
                           int E) {                 // F=8, node-indexed hs
    int e = blockIdx.x * blockDim.x + threadIdx.x;
    if (e >= E) return;
    int s = src[e];
    int d = dst[e];
    uint4 q = *reinterpret_cast<const uint4*>(hs + (size_t)s * 8);
    float2 f0 = h2f2(q.x), f1 = h2f2(q.y), f2 = h2f2(q.z), f3 = h2f2(q.w);
    float4 v0 = make_float4(f0.x, f0.y, f1.x, f1.y);
    float4 v1 = make_float4(f2.x, f2.y, f3.x, f3.y);
    float4* base = reinterpret_cast<float4*>(acc) + d * 2;
    red_add_v4(base,     v0);
    red_add_v4(base + 1, v1);
}

__global__ void k_finalize8(const float* __restrict__ acc,
                            const __half* __restrict__ hs,
                            const int* __restrict__ cnt,
                            const float* __restrict__ bias,
                            float* __restrict__ out,
                            int total4) {           // F=8
    int idx = blockIdx.x * blockDim.x + threadIdx.x;
    if (idx >= total4) return;
    int n = idx >> 1;
    int c = idx & 1;
    float dv = rsqrtf((float)cnt[n] + 1.0f);
    float4 a = reinterpret_cast<const float4*>(acc)[idx];
    uint2 q = *reinterpret_cast<const uint2*>(hs + (size_t)n * 8 + c * 4);
    float2 f0 = h2f2(q.x), f1 = h2f2(q.y);
    float4 b = reinterpret_cast<const float4*>(bias)[c];
    a.x = (a.x + f0.x) * dv + b.x;
    a.y = (a.y + f0.y) * dv + b.y;
    a.z = (a.z + f1.x) * dv + b.z;
    a.w = (a.w + f1.y) * dv + b.w;
    reinterpret_cast<float4*>(out)[idx] = a;
}

// ---------------- host side -------------------------------------------------

extern "C" void kernel_launch(void* const* d_in, const int* in_sizes, int n_in,
                              void* d_out, int out_size) {
    const float* z   = (const float*)d_in[0];
    const int*   e1  = (const int*)d_in[1];
    const int*   ps2 = (const int*)d_in[2];
    const int*   ps1 = (const int*)d_in[3];
    const int*   ps0 = (const int*)d_in[4];
    const float* W1 = (const float*)d_in[5];
    const float* b1 = (const float*)d_in[6];
    const float* W2 = (const float*)d_in[7];
    const float* b2 = (const float*)d_in[8];
    const float* W3 = (const float*)d_in[9];
    const float* b3 = (const float*)d_in[10];
    const float* W4 = (const float*)d_in[11];
    const float* b4 = (const float*)d_in[12];

    const int h2 = 256, h1 = 128, h0 = 64;
    int N = in_sizes[0] / h2;                   // 25000
    int E1 = in_sizes[1] / 2;
    int E2 = in_sizes[2] / 2;
    int E3 = in_sizes[3] / 2;
    int E4 = in_sizes[4] / 2;

    int *cnt, *adj;
    float *hsf, *acc4, *p1, *p2;
    cudaGetSymbolAddress((void**)&cnt,  g_cnt);
    cudaGetSymbolAddress((void**)&adj,  g_adj);
    cudaGetSymbolAddress((void**)&hsf,  g_hs);
    cudaGetSymbolAddress((void**)&acc4, g_acc4);
    cudaGetSymbolAddress((void**)&p1,   g_p1);
    cudaGetSymbolAddress((void**)&p2,   g_p2);
    __half* hs = (__half*)hsf;

    const int OFF1 = 0, OFF2 = 25000, OFF3 = 75000, OFF4 = 175000;

    // ---- phase 0: graph prep (memset + one fused kernel) ----
    cudaMemsetAsync(cnt, 0, (size_t)NTOT * sizeof(int));
    int Etot = E1 + E2 + E3 + E4;
    int gthreads = Etot > NACC4 / 4 ? Etot : NACC4 / 4;
    k_build_all<<<(gthreads + 255) / 256, 256>>>(e1, ps2, ps1, ps0,
                                                 E1, E2, E3, E4, cnt, adj,
                                                 (float4*)acc4);

    // ---- L1: [N, 256] -> [N, 256], relu, no upsample ----
    {
        dim3 grid(h2 / 128, (N + 63) / 64);
        k_gemm_wmma<128><<<grid, 256>>>(z, W1, hs, cnt + OFF1, N, h2, h2, 0);
        k_agg<256><<<(N + 7) / 8, 256>>>(adj + (size_t)OFF1 * CAP, cnt + OFF1,
                                         hs, b1, p1, N, 1);
    }
    // ---- L2: [2N] nodes, 256 -> 128, relu, upsample folded ----
    {
        int M = 2 * N;
        dim3 grid(h1 / 128, (N + 63) / 64);
        k_gemm_wmma<128><<<grid, 256>>>(p1, W2, hs, cnt + OFF2, N, h2, h1, 1);
        k_agg<128><<<(M + 7) / 8, 256>>>(adj + (size_t)OFF2 * CAP, cnt + OFF2,
                                         hs, b2, p2, M, 1);
    }
    // ---- L3: [4N] nodes, 128 -> 64, relu ----
    {
        int M = 4 * N, Mr = 2 * N;
        dim3 grid(1, (Mr + 63) / 64);
        k_gemm_wmma<64><<<grid, 256>>>(p2, W3, hs, cnt + OFF3, Mr, h1, h0, 1);
        k_agg<64><<<(M + 7) / 8, 256>>>(adj + (size_t)OFF3 * CAP, cnt + OFF3,
                                        hs, b3, p1, M, 1);
    }
    // ---- L4: [8N] nodes, 64 -> 8, no relu, straight to d_out ----
    {
        int M = 8 * N, Mr = 4 * N;
        k_gemm_small<<<(Mr + 31) / 32, 256>>>(p1, W4, hs, cnt + OFF4, Mr);
        const int* srcL4 = ps0;
        const int* dstL4 = ps0 + E4;
        k_scatter8<<<(E4 + 255) / 256, 256>>>(srcL4, dstL4, hs, acc4, E4);
        int tot4 = M * 2;
        k_finalize8<<<(tot4 + 255) / 256, 256>>>(acc4, hs, cnt + OFF4, b4,
                                                 (float*)d_out, tot4);
    }
}